// round 11
// baseline (speedup 1.0000x reference)
#include <cuda_runtime.h>
#include <cuda.h>
#include <cuda_fp16.h>
#include <cstdint>
#include <math.h>

#define B_   16
#define N_   2048
#define F_   64
#define HD   256
#define GD   18
#define KD   128
#define FUSE 274
#define LN_EPS 1e-5f

#if defined(__CUDA_ARCH_FEAT_SM103_ALL) || defined(__CUDA_ARCH_FEAT_SM100_ALL) || \
    defined(__CUDA_ARCH_FEAT_SM101_ALL) || \
    (defined(__CUDA_ARCH_SPECIFIC__) && (__CUDA_ARCH_SPECIFIC__ >= 1000)) || \
    (defined(__CUDA_ARCH_FAMILY_SPECIFIC__) && (__CUDA_ARCH_FAMILY_SPECIFIC__ >= 1000))
#define TC_OK 1
#else
#define TC_OK 0
#endif

__device__ __align__(1024) __half g_P1h[B_ * HD * N_];
__device__ __align__(1024) __half g_P2h[B_ * HD * N_];
__device__ __align__(1024) __half g_Ah[(size_t)B_ * N_ * N_];
__device__ __align__(1024) float  g_WT1[HD * F_];
__device__ __align__(1024) __half g_WT2h[HD * HD];
__device__ float g_colsum[B_ * HD];

struct h4 { __half2 a, b; };

__device__ __forceinline__ uint32_t smem_u32(const void* p) {
    uint32_t a;
    asm("{ .reg .u64 t; cvta.to.shared.u64 t, %1; cvt.u32.u64 %0, t; }" : "=r"(a) : "l"(p));
    return a;
}
#define SWZ(x)   ((x) ^ (((x) >> 3) & 0x70))
#define SWZ64(x) ((x) ^ (((x) >> 3) & 0x30))
#define MBAR_INIT(a, c) \
    asm volatile("mbarrier.init.shared.b64 [%0], %1;" :: "r"(a), "r"(c) : "memory")
#define MBAR_EXPECT_TX(a, n) \
    asm volatile("mbarrier.arrive.expect_tx.shared.b64 _, [%0], %1;" :: "r"(a), "r"(n) : "memory")
#define FENCE_ASYNC() asm volatile("fence.proxy.async.shared::cta;" ::: "memory")

__device__ __forceinline__ void mbar_wait(uint32_t mbar, uint32_t parity) {
    asm volatile(
        "{\n\t.reg .pred P1;\n\t"
        "WL_%=:\n\t"
        "mbarrier.try_wait.parity.acquire.cta.shared::cta.b64 P1, [%0], %1, 0x989680;\n\t"
        "@P1 bra.uni WD_%=;\n\t"
        "bra.uni WL_%=;\n\t"
        "WD_%=:\n\t}"
        :: "r"(mbar), "r"(parity) : "memory");
}

#if TC_OK
__device__ __forceinline__ uint64_t sdesc(uint32_t addr) {      // SW128
    return ((2ull << 61) | (1ull << 46) | (64ull << 32) | (1ull << 16))
         | ((uint64_t)(addr >> 4) & 0x3FFF);
}
__device__ __forceinline__ uint64_t sdesc64(uint32_t addr) {    // SW64
    return ((4ull << 61) | (1ull << 46) | (32ull << 32) | (1ull << 16))
         | ((uint64_t)(addr >> 4) & 0x3FFF);
}
__device__ __forceinline__ void tma2d(uint32_t dst, const CUtensorMap* m, int x, int y,
                                      uint32_t mbar) {
    asm volatile(
        "cp.async.bulk.tensor.2d.shared::cta.global.tile.mbarrier::complete_tx::bytes "
        "[%0], [%1, {%2, %3}], [%4];"
        :: "r"(dst), "l"(m), "r"(x), "r"(y), "r"(mbar) : "memory");
}
#define TC_COMMIT(a) \
    asm volatile("tcgen05.commit.cta_group::1.mbarrier::arrive::one.shared::cluster.b64 [%0];" \
                 :: "r"(a) : "memory")
#define TC_ALLOC(a, n) \
    asm volatile("tcgen05.alloc.cta_group::1.sync.aligned.shared::cta.b32 [%0], %1;" \
                 :: "r"(a), "r"(n) : "memory")
#define TC_RELINQ() \
    asm volatile("tcgen05.relinquish_alloc_permit.cta_group::1.sync.aligned;")
#define TC_DEALLOC(t, n) \
    asm volatile("tcgen05.dealloc.cta_group::1.sync.aligned.b32 %0, %1;" :: "r"(t), "r"(n))
#define TC_FENCE_AFTER()  asm volatile("tcgen05.fence::after_thread_sync;" ::: "memory")
#define TC_FENCE_BEFORE() asm volatile("tcgen05.fence::before_thread_sync;" ::: "memory")
#define TC_WAIT_LD() asm volatile("tcgen05.wait::ld.sync.aligned;" ::: "memory")

#define IDESC_TF32 ((1u << 4) | (2u << 7) | (2u << 10) | (32u << 17) | (8u << 24))
#define IDESC_F16  ((1u << 4) | (32u << 17) | (8u << 24))

__device__ __forceinline__ void mma_tf32(uint32_t d, uint64_t ad, uint64_t bd, uint32_t acc) {
    asm volatile(
        "{\n\t.reg .pred p;\n\tsetp.ne.u32 p, %4, 0;\n\t"
        "tcgen05.mma.cta_group::1.kind::tf32 [%0], %1, %2, %3, p;\n\t}"
        :: "r"(d), "l"(ad), "l"(bd), "r"(IDESC_TF32), "r"(acc) : "memory");
}
__device__ __forceinline__ void mma_f16(uint32_t d, uint64_t ad, uint64_t bd, uint32_t acc) {
    asm volatile(
        "{\n\t.reg .pred p;\n\tsetp.ne.u32 p, %5, 0;\n\t"
        "tcgen05.mma.cta_group::1.kind::f16 [%0], %1, %2, %3, {%4, %4, %4, %4}, p;\n\t}"
        :: "r"(d), "l"(ad), "l"(bd), "r"(IDESC_F16), "r"(0u), "r"(acc) : "memory");
}

#define LDX32(r, a) \
    asm volatile( \
        "tcgen05.ld.sync.aligned.32x32b.x32.b32 " \
        "{%0, %1, %2, %3, %4, %5, %6, %7, %8, %9, %10, %11, %12, %13, %14, %15, " \
        " %16, %17, %18, %19, %20, %21, %22, %23, %24, %25, %26, %27, %28, %29, %30, %31}, [%32];" \
        : "=r"((r)[0]),  "=r"((r)[1]),  "=r"((r)[2]),  "=r"((r)[3]), \
          "=r"((r)[4]),  "=r"((r)[5]),  "=r"((r)[6]),  "=r"((r)[7]), \
          "=r"((r)[8]),  "=r"((r)[9]),  "=r"((r)[10]), "=r"((r)[11]), \
          "=r"((r)[12]), "=r"((r)[13]), "=r"((r)[14]), "=r"((r)[15]), \
          "=r"((r)[16]), "=r"((r)[17]), "=r"((r)[18]), "=r"((r)[19]), \
          "=r"((r)[20]), "=r"((r)[21]), "=r"((r)[22]), "=r"((r)[23]), \
          "=r"((r)[24]), "=r"((r)[25]), "=r"((r)[26]), "=r"((r)[27]), \
          "=r"((r)[28]), "=r"((r)[29]), "=r"((r)[30]), "=r"((r)[31]) \
        : "r"(a))
#endif

// ---------------------------------------------------------------------------
__global__ __launch_bounds__(256) void k_prep(const float* __restrict__ W1,
                                              const float* __restrict__ W2) {
    const int t = threadIdx.x, bx = blockIdx.x;     // grid 256
    if (bx < 16) g_colsum[bx * 256 + t] = 0.f;
    if (bx < F_) g_WT1[t * F_ + bx] = W1[bx * 256 + t];
    g_WT2h[t * HD + bx] = __float2half(W2[bx * 256 + t]);
}

// ---------------------------------------------------------------------------
// Small GEMM (tf32): P1h^T = (X @ W1)^T, output fp16
// ---------------------------------------------------------------------------
__global__ __launch_bounds__(128, 1)
void k_small_gemm(const __grid_constant__ CUtensorMap mapIn,
                  const __grid_constant__ CUtensorMap mapW,
                  const float* __restrict__ In) {
    const int tid = threadIdx.x, b = blockIdx.y, m0 = blockIdx.x * 128;
    __half* PTb = g_P1h + (size_t)b * HD * N_;
#if TC_OK
    constexpr int STG = 48 * 1024;
    extern __shared__ char dyn[];
    const uint32_t sbase = (smem_u32(dyn) + 1023) & ~1023u;
    __shared__ __align__(8) uint64_t s_bar[3];
    __shared__ uint32_t s_tmem[1];
    const int wid = tid >> 5, lane = tid & 31;
    const uint32_t bar0 = smem_u32(s_bar);

    if (tid == 0) for (int i = 0; i < 3; i++) MBAR_INIT(bar0 + i * 8, 1);
    if (wid == 0) { TC_ALLOC(smem_u32(s_tmem), 256); TC_RELINQ(); }
    __syncthreads();
    uint32_t tmem;
    asm volatile("ld.shared.b32 %0, [%1];" : "=r"(tmem) : "r"(smem_u32(s_tmem)));

    if (tid == 0) {
        const int yA = b * N_ + m0;
        for (int t = 0; t < 2; t++) {
            uint32_t sa = sbase + t * STG;
            MBAR_EXPECT_TX(bar0 + t * 8, STG);
            tma2d(sa,             &mapIn, t * 32, yA, bar0 + t * 8);
            tma2d(sa + 16 * 1024, &mapW,  t * 32, 0,  bar0 + t * 8);
        }
        for (int t = 0; t < 2; t++) {
            mbar_wait(bar0 + t * 8, 0);
            uint64_t a0 = sdesc(sbase + t * STG), b0 = sdesc(sbase + t * STG + 16 * 1024);
#pragma unroll
            for (int ks = 0; ks < 4; ks++)
                mma_tf32(tmem, a0 + ks * 2, b0 + ks * 2, (t > 0 || ks > 0) ? 1u : 0u);
        }
        TC_COMMIT(bar0 + 16);
    }
    mbar_wait(bar0 + 16, 0);
    TC_FENCE_AFTER();
    const int row = m0 + wid * 32 + lane;
#pragma unroll
    for (int c8 = 0; c8 < 8; c8++) {
        uint32_t r[32];
        LDX32(r, tmem + c8 * 32); TC_WAIT_LD();
#pragma unroll
        for (int j = 0; j < 32; j++)
            PTb[(size_t)(c8 * 32 + j) * N_ + row] = __float2half(__uint_as_float(r[j]));
    }
    __syncthreads();
    if (wid == 0) TC_DEALLOC(tmem, 256);
#else
    for (int idx = tid; idx < 128 * 256; idx += 128) {
        int m = idx >> 8, c = idx & 255;
        float acc = 0.f;
        const float* Inb = In + (size_t)b * N_ * F_ + (size_t)(m0 + m) * F_;
        for (int k = 0; k < F_; k++) acc += Inb[k] * g_WT1[(size_t)c * F_ + k];
        PTb[(size_t)c * N_ + m0 + m] = __float2half(acc);
    }
#endif
}

// ---------------------------------------------------------------------------
// Fused layer-1: A fp32 TMA -> smem; 127 threads convert -> SW64 fp16 ring
// (MMA operand) AND stream to g_Ah for big2. f16 MMA, k=32 chunks, NK=64.
// Epilogue: y = relu(LN(D+b1)); P2h = (y @ W2)^T (f16 GEMM).
// ---------------------------------------------------------------------------
__global__ __launch_bounds__(128, 1)
void k_fused1(const __grid_constant__ CUtensorMap mapA32,
              const __grid_constant__ CUtensorMap mapPh,
              const __grid_constant__ CUtensorMap mapW2h,
              const float* __restrict__ A,
              const float* __restrict__ bias, const float* __restrict__ gamma,
              const float* __restrict__ beta) {
    extern __shared__ char dyn[];
    const int tid = threadIdx.x, b = blockIdx.y, m0 = blockIdx.x * 256;
#if TC_OK
    constexpr int NK = 64;
    constexpr int A32OFF = 0;           // 3 x 32KB
    constexpr int POFF   = 96 * 1024;   // 3 x 16KB
    constexpr int A16OFF = 144 * 1024;  // 3 x 16KB
    constexpr int W2OFF  = 64 * 1024;   // epilogue (after drain)
    const uint32_t sbase = (smem_u32(dyn) + 1023) & ~1023u;
    const uint32_t abase = sbase - smem_u32(dyn);
    __shared__ __align__(8) uint64_t s_bar[11];
    __shared__ uint32_t s_tmem[1];
    __shared__ float sb[256], sg[256], st[256];
    const int wid = tid >> 5, lane = tid & 31;
    const uint32_t bar0 = smem_u32(s_bar);
    // bars: full[3]=+0, empty[3]=+24, final=+48, ef[2]=+56, ee=+72, efin=+80

    if (tid == 0) for (int i = 0; i < 11; i++) MBAR_INIT(bar0 + i * 8, 1);
    if (wid == 0) { TC_ALLOC(smem_u32(s_tmem), 512); TC_RELINQ(); }
    __syncthreads();
    uint32_t tmem;
    asm volatile("ld.shared.b32 %0, [%1];" : "=r"(tmem) : "r"(smem_u32(s_tmem)));

    if (tid != 0)
        for (int i = tid - 1; i < 256; i += 127) {
            sb[i] = bias[i]; sg[i] = gamma[i]; st[i] = beta[i];
        }
    __syncthreads();

    const int yA = b * N_ + m0, yB = b * HD;
    auto issue = [&](int t) {
        int s = t % 3;
        MBAR_EXPECT_TX(bar0 + s * 8, 49152);
        tma2d(sbase + A32OFF + s * 32768, &mapA32, t * 32, yA, bar0 + s * 8);
        tma2d(sbase + POFF   + s * 16384, &mapPh,  t * 32, yB, bar0 + s * 8);
    };
    if (tid == 0) { issue(0); issue(1); issue(2); }

    int fp[3] = {0, 0, 0}, ep[3] = {0, 0, 0};
    __half* AhB = g_Ah + (size_t)b * N_ * N_ + (size_t)m0 * N_;
#pragma unroll 1
    for (int t = 0; t < NK; t++) {
        int s = t % 3;
        mbar_wait(bar0 + s * 8, fp[s]); fp[s] ^= 1;    // all threads
        if (tid != 0) {
            // convert A32[s] (256 rows x 32 f) -> A16[s] SW64 (+ stream to g_Ah)
            const float4* src = (const float4*)(dyn + abase + A32OFF + s * 32768);
            char* d16 = dyn + abase + A16OFF + s * 16384;
            const int k0 = t * 32;
#pragma unroll 1
            for (int i = tid - 1; i < 2048; i += 127) {
                int r = i >> 3, c4 = i & 7;
                float4 v = src[i];
                h4 h;
                h.a = __floats2half2_rn(v.x, v.y);
                h.b = __floats2half2_rn(v.z, v.w);
                int half_t = r >> 7, rl = r & 127;
                *(h4*)(d16 + (half_t << 13) + SWZ64(rl * 64 + c4 * 8)) = h;
                *(h4*)(AhB + (size_t)r * N_ + k0 + c4 * 4) = h;
            }
            TC_FENCE_BEFORE();
            FENCE_ASYNC();
        }
        __syncthreads();
        if (tid == 0) {
            uint64_t a0 = sdesc64(sbase + A16OFF + s * 16384);
            uint64_t a1 = sdesc64(sbase + A16OFF + s * 16384 + 8192);
            uint64_t b0 = sdesc64(sbase + POFF + s * 16384);
#pragma unroll
            for (int ks = 0; ks < 2; ks++) {
                uint32_t acc = (t > 0 || ks > 0) ? 1u : 0u;
                mma_f16(tmem,       a0 + ks * 2, b0 + ks * 2, acc);
                mma_f16(tmem + 256, a1 + ks * 2, b0 + ks * 2, acc);
            }
            TC_COMMIT(bar0 + 24 + s * 8);
            int tn = t + 3;
            if (tn < NK) { mbar_wait(bar0 + 24 + s * 8, ep[s]); ep[s] ^= 1; issue(tn); }
        }
    }
    if (tid == 0) TC_COMMIT(bar0 + 48);
    mbar_wait(bar0 + 48, 0);
    __syncthreads();
    TC_FENCE_AFTER();

    // ---- epilogue: LN+ReLU; f16 GEMM P2 = y @ W2 ----
    int efp[2] = {0, 0}, eep = 0;
    auto issueW2 = [&](int chunk, int s) {      // chunk 0..3, each k=64
        MBAR_EXPECT_TX(bar0 + 56 + s * 8, 32768);
        tma2d(sbase + W2OFF + s * 32768, &mapW2h, chunk * 64, 0, bar0 + 56 + s * 8);
    };
    if (tid == 0) { issueW2(0, 0); issueW2(1, 1); }

#pragma unroll 1
    for (int half = 0; half < 2; half++) {
        const int row = wid * 32 + lane;
        const uint32_t dbase = tmem + half * 256;
        float sum = 0.f, sq = 0.f;
#pragma unroll 1
        for (int c8 = 0; c8 < 8; c8++) {
            uint32_t r[32];
            LDX32(r, dbase + c8 * 32); TC_WAIT_LD();
#pragma unroll
            for (int j = 0; j < 32; j++) {
                float v = __uint_as_float(r[j]) + sb[c8 * 32 + j];
                sum += v; sq += v * v;
            }
        }
        const float mu = sum * (1.f / HD);
        const float rs = rsqrtf(sq * (1.f / HD) - mu * mu + LN_EPS);

#pragma unroll 1
        for (int c8 = 0; c8 < 8; c8++) {
            uint32_t r[32];
            LDX32(r, dbase + c8 * 32); TC_WAIT_LD();
            float y[32];
#pragma unroll
            for (int j = 0; j < 32; j++) {
                float v = __uint_as_float(r[j]) + sb[c8 * 32 + j];
                y[j] = fmaxf((v - mu) * rs * sg[c8 * 32 + j] + st[c8 * 32 + j], 0.f);
            }
            char* ybase = dyn + abase + (c8 >> 1) * 16384;
            const int off = (c8 & 1) * 64;
#pragma unroll
            for (int q = 0; q < 4; q++) {
                __half2 h[4];
#pragma unroll
                for (int p = 0; p < 4; p++)
                    h[p] = __floats2half2_rn(y[q * 8 + 2 * p], y[q * 8 + 2 * p + 1]);
                *(float4*)(ybase + SWZ(row * 128 + off + q * 16)) = *(float4*)h;
            }
        }
        TC_FENCE_BEFORE();
        FENCE_ASYNC();
        __syncthreads();

        if (tid == 0) {
#pragma unroll 1
            for (int c = 0; c < 4; c++) {
                int s = c & 1;
                mbar_wait(bar0 + 56 + s * 8, efp[s]); efp[s] ^= 1;
                uint64_t yd = sdesc(sbase + c * 16384);
                uint64_t wd = sdesc(sbase + W2OFF + s * 32768);
#pragma unroll
                for (int ks = 0; ks < 4; ks++)
                    mma_f16(tmem + half * 256, yd + ks * 2, wd + ks * 2,
                            (c > 0 || ks > 0) ? 1u : 0u);
                TC_COMMIT(bar0 + 72);
                mbar_wait(bar0 + 72, eep & 1); eep++;
                int nxt = c + 2;
                if (nxt < 4)        issueW2(nxt, s);
                else if (half == 0) issueW2(nxt - 4, s);
            }
            TC_COMMIT(bar0 + 80);
        }
        mbar_wait(bar0 + 80, half);
        TC_FENCE_AFTER();

        __half* PTb = g_P2h + (size_t)b * HD * N_;
        const int grow = m0 + half * 128 + row;
#pragma unroll 1
        for (int c8 = 0; c8 < 8; c8++) {
            uint32_t r[32];
            LDX32(r, dbase + c8 * 32); TC_WAIT_LD();
#pragma unroll
            for (int j = 0; j < 32; j++)
                PTb[(size_t)(c8 * 32 + j) * N_ + grow] = __float2half(__uint_as_float(r[j]));
        }
        TC_FENCE_BEFORE();
        __syncthreads();
    }
    if (wid == 0) TC_DEALLOC(tmem, 512);
#else
    const float* Ab = A + (size_t)b * N_ * N_ + (size_t)m0 * N_;
    const __half* Bb = g_P1h + (size_t)b * HD * N_;
    __half* PTb = g_P2h + (size_t)b * HD * N_;
    __shared__ float arow[N_];
    __shared__ float drow[256];
    __shared__ float red[2][4];
    const int lane = tid & 31, wid = tid >> 5;
    for (int m = 0; m < 256; m++) {
        for (int i = tid; i < N_ / 4; i += 128)
            ((float4*)arow)[i] = ((const float4*)(Ab + (size_t)m * N_))[i];
        __syncthreads();
        for (int cp = 0; cp < 2; cp++) {
            int c = tid + cp * 128;
            float acc = 0.f;
            const __half* Brow = Bb + (size_t)c * N_;
            for (int k = 0; k < N_; k++) acc += arow[k] * __half2float(Brow[k]);
            drow[c] = acc + bias[c];
        }
        __syncthreads();
        float v0 = drow[tid], v1 = drow[tid + 128];
        float s = v0 + v1, q = v0 * v0 + v1 * v1;
        for (int o = 16; o > 0; o >>= 1) {
            s += __shfl_xor_sync(0xffffffff, s, o);
            q += __shfl_xor_sync(0xffffffff, q, o);
        }
        if (lane == 0) { red[0][wid] = s; red[1][wid] = q; }
        __syncthreads();
        float ts = red[0][0] + red[0][1] + red[0][2] + red[0][3];
        float tq = red[1][0] + red[1][1] + red[1][2] + red[1][3];
        float mu = ts * (1.f / HD);
        float rsv = rsqrtf(tq * (1.f / HD) - mu * mu + LN_EPS);
        drow[tid]       = fmaxf((v0 - mu) * rsv * gamma[tid] + beta[tid], 0.f);
        drow[tid + 128] = fmaxf((v1 - mu) * rsv * gamma[tid + 128] + beta[tid + 128], 0.f);
        __syncthreads();
        for (int cp = 0; cp < 2; cp++) {
            int c = tid + cp * 128;
            float acc = 0.f;
            for (int k = 0; k < HD; k++)
                acc += drow[k] * __half2float(g_WT2h[(size_t)c * HD + k]);
            PTb[(size_t)c * N_ + m0 + m] = __float2half(acc);
        }
        __syncthreads();
    }
#endif
}

// ---------------------------------------------------------------------------
// Layer-2 big GEMM (FP16): colsum += relu(LN(A_h @ P2h^T + b2))
// ---------------------------------------------------------------------------
__global__ __launch_bounds__(128, 1)
void k_big2(const __grid_constant__ CUtensorMap mapAh,
            const __grid_constant__ CUtensorMap mapPh,
            const float* __restrict__ A,
            const float* __restrict__ bias, const float* __restrict__ gamma,
            const float* __restrict__ beta) {
    extern __shared__ char dyn[];
    const int tid = threadIdx.x, b = blockIdx.y, m0 = blockIdx.x * 256;
#if TC_OK
    constexpr int NK = 32, STG = 64 * 1024;
    const uint32_t sbase = (smem_u32(dyn) + 1023) & ~1023u;
    __shared__ __align__(8) uint64_t s_bar[7];
    __shared__ uint32_t s_tmem[1];
    __shared__ float sb[256], sg[256], st[256];
    const int wid = tid >> 5, lane = tid & 31;
    const uint32_t bar0 = smem_u32(s_bar);

    if (tid == 0) for (int i = 0; i < 7; i++) MBAR_INIT(bar0 + i * 8, 1);
    if (wid == 0) { TC_ALLOC(smem_u32(s_tmem), 512); TC_RELINQ(); }
    __syncthreads();
    uint32_t tmem;
    asm volatile("ld.shared.b32 %0, [%1];" : "=r"(tmem) : "r"(smem_u32(s_tmem)));

    if (tid != 0)
        for (int i = tid - 1; i < 256; i += 127) {
            sb[i] = bias[i]; sg[i] = gamma[i]; st[i] = beta[i];
        }

    if (tid == 0) {
        int fp[3] = {0, 0, 0}, ep[3] = {0, 0, 0};
        const int yA = b * N_ + m0, yB = b * HD;
        auto issue = [&](int t) {
            int s = t % 3;
            uint32_t sa = sbase + s * STG;
            MBAR_EXPECT_TX(bar0 + s * 8, STG);
            tma2d(sa,             &mapAh, t * 64, yA, bar0 + s * 8);
            tma2d(sa + 32 * 1024, &mapPh, t * 64, yB, bar0 + s * 8);
        };
        issue(0); issue(1); issue(2);
#pragma unroll 1
        for (int t = 0; t < NK; t++) {
            int s = t % 3;
            mbar_wait(bar0 + s * 8, fp[s]); fp[s] ^= 1;
            uint64_t a0 = sdesc(sbase + s * STG);
            uint64_t a1 = sdesc(sbase + s * STG + 16 * 1024);
            uint64_t b0 = sdesc(sbase + s * STG + 32 * 1024);
#pragma unroll
            for (int ks = 0; ks < 4; ks++) {
                uint32_t acc = (t > 0 || ks > 0) ? 1u : 0u;
                mma_f16(tmem,       a0 + ks * 2, b0 + ks * 2, acc);
                mma_f16(tmem + 256, a1 + ks * 2, b0 + ks * 2, acc);
            }
            TC_COMMIT(bar0 + 24 + s * 8);
            int tn = t + 3;
            if (tn < NK) { mbar_wait(bar0 + 24 + s * 8, ep[s]); ep[s] ^= 1; issue(tn); }
        }
        TC_COMMIT(bar0 + 48);
    }
    mbar_wait(bar0 + 48, 0);
    TC_FENCE_AFTER();

    float* wsc = (float*)(dyn) + wid * 33 * 32;
#pragma unroll 1
    for (int half = 0; half < 2; half++) {
        const uint32_t dbase = tmem + half * 256;
        float sum = 0.f, sq = 0.f;
#pragma unroll 1
        for (int c8 = 0; c8 < 8; c8++) {
            uint32_t r[32];
            LDX32(r, dbase + c8 * 32); TC_WAIT_LD();
#pragma unroll
            for (int j = 0; j < 32; j++) {
                float v = __uint_as_float(r[j]) + sb[c8 * 32 + j];
                sum += v; sq += v * v;
            }
        }
        const float mu = sum * (1.f / HD);
        const float rs = rsqrtf(sq * (1.f / HD) - mu * mu + LN_EPS);
#pragma unroll 1
        for (int c8 = 0; c8 < 8; c8++) {
            uint32_t r[32];
            LDX32(r, dbase + c8 * 32); TC_WAIT_LD();
#pragma unroll
            for (int j = 0; j < 32; j++) {
                float v = __uint_as_float(r[j]) + sb[c8 * 32 + j];
                wsc[lane * 33 + j] =
                    fmaxf((v - mu) * rs * sg[c8 * 32 + j] + st[c8 * 32 + j], 0.f);
            }
            __syncwarp();
            float s2 = 0.f;
#pragma unroll
            for (int r2 = 0; r2 < 32; r2++) s2 += wsc[r2 * 33 + lane];
            atomicAdd(&g_colsum[b * HD + c8 * 32 + lane], s2);
            __syncwarp();
        }
    }
    __syncthreads();
    if (wid == 0) TC_DEALLOC(tmem, 512);
#else
    const float* Ab = A + (size_t)b * N_ * N_ + (size_t)m0 * N_;
    const __half* Bb = g_P2h + (size_t)b * HD * N_;
    __shared__ float arow[N_];
    __shared__ float drow[256];
    __shared__ float red[2][4];
    const int lane = tid & 31, wid = tid >> 5;
    float csum0 = 0.f, csum1 = 0.f;
    for (int m = 0; m < 256; m++) {
        for (int i = tid; i < N_ / 4; i += 128)
            ((float4*)arow)[i] = ((const float4*)(Ab + (size_t)m * N_))[i];
        __syncthreads();
        for (int cp = 0; cp < 2; cp++) {
            int c = tid + cp * 128;
            float acc = 0.f;
            const __half* Brow = Bb + (size_t)c * N_;
            for (int k = 0; k < N_; k++) acc += arow[k] * __half2float(Brow[k]);
            drow[c] = acc + bias[c];
        }
        __syncthreads();
        float v0 = drow[tid], v1 = drow[tid + 128];
        float s = v0 + v1, q = v0 * v0 + v1 * v1;
        for (int o = 16; o > 0; o >>= 1) {
            s += __shfl_xor_sync(0xffffffff, s, o);
            q += __shfl_xor_sync(0xffffffff, q, o);
        }
        if (lane == 0) { red[0][wid] = s; red[1][wid] = q; }
        __syncthreads();
        float ts = red[0][0] + red[0][1] + red[0][2] + red[0][3];
        float tq = red[1][0] + red[1][1] + red[1][2] + red[1][3];
        float mu = ts * (1.f / HD);
        float rsv = rsqrtf(tq * (1.f / HD) - mu * mu + LN_EPS);
        csum0 += fmaxf((v0 - mu) * rsv * gamma[tid] + beta[tid], 0.f);
        csum1 += fmaxf((v1 - mu) * rsv * gamma[tid + 128] + beta[tid + 128], 0.f);
        __syncthreads();
    }
    atomicAdd(&g_colsum[b * HD + tid], csum0);
    atomicAdd(&g_colsum[b * HD + tid + 128], csum1);
#endif
}

// ---------------------------------------------------------------------------
__global__ __launch_bounds__(288)
void k_finalize(const float* __restrict__ gvec,
                const float* __restrict__ Ws, const float* __restrict__ bs,
                const float* __restrict__ Wa, const float* __restrict__ ba,
                float* __restrict__ out) {
    __shared__ float fused[FUSE];
    const int b = blockIdx.x, t = threadIdx.x;
    if (t < HD)        fused[t] = g_colsum[b * HD + t] * (1.f / N_);
    else if (t < FUSE) fused[t] = gvec[b * GD + (t - HD)];
    __syncthreads();
    if (t < KD) {
        float a = ba[t];
        for (int i = 0; i < FUSE; i++) a += fused[i] * Wa[i * KD + t];
        out[B_ + b * KD + t] = a;
    } else if (t == KD) {
        float a = bs[0];
        for (int i = 0; i < FUSE; i++) a += fused[i] * Ws[i];
        out[b] = a;
    }
}

// ---------------------------------------------------------------------------
typedef CUresult (CUDAAPI *tmap_enc_t)(
    CUtensorMap*, CUtensorMapDataType, cuuint32_t, void*,
    const cuuint64_t*, const cuuint64_t*, const cuuint32_t*, const cuuint32_t*,
    CUtensorMapInterleave, CUtensorMapSwizzle, CUtensorMapL2promotion,
    CUtensorMapFloatOOBfill);

static void make_map(tmap_enc_t enc, CUtensorMap* m, const void* ptr,
                     CUtensorMapDataType dt, CUtensorMapSwizzle sw,
                     uint64_t d0, uint64_t d1, uint64_t stride1_bytes,
                     uint32_t box0, uint32_t box1) {
    cuuint64_t dims[2]    = {d0, d1};
    cuuint64_t strides[1] = {stride1_bytes};
    cuuint32_t box[2]     = {box0, box1};
    cuuint32_t es[2]      = {1, 1};
    enc(m, dt, 2, (void*)ptr, dims, strides, box, es,
        CU_TENSOR_MAP_INTERLEAVE_NONE, sw,
        CU_TENSOR_MAP_L2_PROMOTION_L2_128B, CU_TENSOR_MAP_FLOAT_OOB_FILL_NONE);
}

extern "C" void kernel_launch(void* const* d_in, const int* in_sizes, int n_in,
                              void* d_out, int out_size) {
    const float* A    = (const float*)d_in[0];
    const float* X    = (const float*)d_in[1];
    const float* gvec = (const float*)d_in[2];
    const float* W1   = (const float*)d_in[3];
    const float* b1   = (const float*)d_in[4];
    const float* g1   = (const float*)d_in[5];
    const float* be1  = (const float*)d_in[6];
    const float* W2   = (const float*)d_in[7];
    const float* b2   = (const float*)d_in[8];
    const float* g2   = (const float*)d_in[9];
    const float* be2  = (const float*)d_in[10];
    const float* Ws   = (const float*)d_in[11];
    const float* bs   = (const float*)d_in[12];
    const float* Wa   = (const float*)d_in[13];
    const float* ba   = (const float*)d_in[14];
    float* out = (float*)d_out;

    const int SMALL_SMEM = 2 * 48 * 1024 + 1024;
    const int F1_SMEM    = 192 * 1024 + 1024;
    const int BIG_SMEM   = 3 * 64 * 1024 + 1024;
    cudaFuncSetAttribute(k_small_gemm, cudaFuncAttributeMaxDynamicSharedMemorySize, SMALL_SMEM);
    cudaFuncSetAttribute(k_fused1,     cudaFuncAttributeMaxDynamicSharedMemorySize, F1_SMEM);
    cudaFuncSetAttribute(k_big2,       cudaFuncAttributeMaxDynamicSharedMemorySize, BIG_SMEM);

    float* WT1;
    __half *P1hp, *P2hp, *Ahp, *W2hp;
    cudaGetSymbolAddress((void**)&WT1,  g_WT1);
    cudaGetSymbolAddress((void**)&P1hp, g_P1h);
    cudaGetSymbolAddress((void**)&P2hp, g_P2h);
    cudaGetSymbolAddress((void**)&Ahp,  g_Ah);
    cudaGetSymbolAddress((void**)&W2hp, g_WT2h);

    tmap_enc_t enc = nullptr;
#if CUDART_VERSION >= 12050
    cudaDriverEntryPointQueryResult qr;
    cudaGetDriverEntryPointByVersion("cuTensorMapEncodeTiled", (void**)&enc, 12000,
                                     cudaEnableDefault, &qr);
#else
    cudaGetDriverEntryPoint("cuTensorMapEncodeTiled", (void**)&enc, cudaEnableDefault);
#endif

    CUtensorMap mX, mW1, mA32, mP1h64, mAh, mP2h, mW2h;
    make_map(enc, &mX,     X,    CU_TENSOR_MAP_DATA_TYPE_FLOAT32, CU_TENSOR_MAP_SWIZZLE_128B,
             F_, (uint64_t)N_ * B_, (uint64_t)F_ * 4, 32, 128);
    make_map(enc, &mW1,    WT1,  CU_TENSOR_MAP_DATA_TYPE_FLOAT32, CU_TENSOR_MAP_SWIZZLE_128B,
             F_, HD, (uint64_t)F_ * 4, 32, 256);
    make_map(enc, &mA32,   A,    CU_TENSOR_MAP_DATA_TYPE_FLOAT32, CU_TENSOR_MAP_SWIZZLE_NONE,
             N_, (uint64_t)N_ * B_, (uint64_t)N_ * 4, 32, 256);
    make_map(enc, &mP1h64, P1hp, CU_TENSOR_MAP_DATA_TYPE_FLOAT16, CU_TENSOR_MAP_SWIZZLE_64B,
             N_, (uint64_t)HD * B_, (uint64_t)N_ * 2, 32, 256);
    make_map(enc, &mAh,    Ahp,  CU_TENSOR_MAP_DATA_TYPE_FLOAT16, CU_TENSOR_MAP_SWIZZLE_128B,
             N_, (uint64_t)N_ * B_, (uint64_t)N_ * 2, 64, 256);
    make_map(enc, &mP2h,   P2hp, CU_TENSOR_MAP_DATA_TYPE_FLOAT16, CU_TENSOR_MAP_SWIZZLE_128B,
             N_, (uint64_t)HD * B_, (uint64_t)N_ * 2, 64, 256);
    make_map(enc, &mW2h,   W2hp, CU_TENSOR_MAP_DATA_TYPE_FLOAT16, CU_TENSOR_MAP_SWIZZLE_128B,
             HD, HD, (uint64_t)HD * 2, 64, 256);

    k_prep<<<256, 256>>>(W1, W2);
    k_small_gemm<<<dim3(N_ / 128, B_), 128, SMALL_SMEM>>>(mX, mW1, X);
    k_fused1<<<dim3(N_ / 256, B_), 128, F1_SMEM>>>(mA32, mP1h64, mW2h, A, b1, g1, be1);
    k_big2<<<dim3(N_ / 256, B_), 128, BIG_SMEM>>>(mAh, mP2h, A, b2, g2, be2);
    k_finalize<<<B_, 288>>>(gvec, Ws, bs, Wa, ba, out);
}

// round 12
// speedup vs baseline: 1.0078x; 1.0078x over previous
#include <cuda_runtime.h>
#include <cuda.h>
#include <cuda_fp16.h>
#include <cstdint>
#include <math.h>

#define B_   16
#define N_   2048
#define F_   64
#define HD   256
#define GD   18
#define KD   128
#define FUSE 274
#define LN_EPS 1e-5f

#if defined(__CUDA_ARCH_FEAT_SM103_ALL) || defined(__CUDA_ARCH_FEAT_SM100_ALL) || \
    defined(__CUDA_ARCH_FEAT_SM101_ALL) || \
    (defined(__CUDA_ARCH_SPECIFIC__) && (__CUDA_ARCH_SPECIFIC__ >= 1000)) || \
    (defined(__CUDA_ARCH_FAMILY_SPECIFIC__) && (__CUDA_ARCH_FAMILY_SPECIFIC__ >= 1000))
#define TC_OK 1
#else
#define TC_OK 0
#endif

__device__ __align__(1024) __half g_P1h[B_ * HD * N_];
__device__ __align__(1024) __half g_P2h[B_ * HD * N_];
__device__ __align__(1024) __half g_Ah[(size_t)B_ * N_ * N_];
__device__ __align__(1024) float  g_WT1[HD * F_];
__device__ __align__(1024) __half g_WT2h[HD * HD];
__device__ float g_colsum[B_ * HD];

struct h4 { __half2 a, b; };

__device__ __forceinline__ uint32_t smem_u32(const void* p) {
    uint32_t a;
    asm("{ .reg .u64 t; cvta.to.shared.u64 t, %1; cvt.u32.u64 %0, t; }" : "=r"(a) : "l"(p));
    return a;
}
#define SWZ(x)   ((x) ^ (((x) >> 3) & 0x70))
#define SWZ64(x) ((x) ^ (((x) >> 3) & 0x30))
#define MBAR_INIT(a, c) \
    asm volatile("mbarrier.init.shared.b64 [%0], %1;" :: "r"(a), "r"(c) : "memory")
#define MBAR_EXPECT_TX(a, n) \
    asm volatile("mbarrier.arrive.expect_tx.shared.b64 _, [%0], %1;" :: "r"(a), "r"(n) : "memory")
#define FENCE_ASYNC() asm volatile("fence.proxy.async.shared::cta;" ::: "memory")

__device__ __forceinline__ void mbar_wait(uint32_t mbar, uint32_t parity) {
    asm volatile(
        "{\n\t.reg .pred P1;\n\t"
        "WL_%=:\n\t"
        "mbarrier.try_wait.parity.acquire.cta.shared::cta.b64 P1, [%0], %1, 0x989680;\n\t"
        "@P1 bra.uni WD_%=;\n\t"
        "bra.uni WL_%=;\n\t"
        "WD_%=:\n\t}"
        :: "r"(mbar), "r"(parity) : "memory");
}

#if TC_OK
__device__ __forceinline__ uint64_t sdesc(uint32_t addr) {      // SW128
    return ((2ull << 61) | (1ull << 46) | (64ull << 32) | (1ull << 16))
         | ((uint64_t)(addr >> 4) & 0x3FFF);
}
__device__ __forceinline__ uint64_t sdesc64(uint32_t addr) {    // SW64
    return ((4ull << 61) | (1ull << 46) | (32ull << 32) | (1ull << 16))
         | ((uint64_t)(addr >> 4) & 0x3FFF);
}
__device__ __forceinline__ void tma2d(uint32_t dst, const CUtensorMap* m, int x, int y,
                                      uint32_t mbar) {
    asm volatile(
        "cp.async.bulk.tensor.2d.shared::cta.global.tile.mbarrier::complete_tx::bytes "
        "[%0], [%1, {%2, %3}], [%4];"
        :: "r"(dst), "l"(m), "r"(x), "r"(y), "r"(mbar) : "memory");
}
#define TC_COMMIT(a) \
    asm volatile("tcgen05.commit.cta_group::1.mbarrier::arrive::one.shared::cluster.b64 [%0];" \
                 :: "r"(a) : "memory")
#define TC_ALLOC(a, n) \
    asm volatile("tcgen05.alloc.cta_group::1.sync.aligned.shared::cta.b32 [%0], %1;" \
                 :: "r"(a), "r"(n) : "memory")
#define TC_RELINQ() \
    asm volatile("tcgen05.relinquish_alloc_permit.cta_group::1.sync.aligned;")
#define TC_DEALLOC(t, n) \
    asm volatile("tcgen05.dealloc.cta_group::1.sync.aligned.b32 %0, %1;" :: "r"(t), "r"(n))
#define TC_FENCE_AFTER()  asm volatile("tcgen05.fence::after_thread_sync;" ::: "memory")
#define TC_FENCE_BEFORE() asm volatile("tcgen05.fence::before_thread_sync;" ::: "memory")
#define TC_WAIT_LD() asm volatile("tcgen05.wait::ld.sync.aligned;" ::: "memory")

#define IDESC_TF32 ((1u << 4) | (2u << 7) | (2u << 10) | (32u << 17) | (8u << 24))
#define IDESC_F16  ((1u << 4) | (32u << 17) | (8u << 24))

__device__ __forceinline__ void mma_tf32(uint32_t d, uint64_t ad, uint64_t bd, uint32_t acc) {
    asm volatile(
        "{\n\t.reg .pred p;\n\tsetp.ne.u32 p, %4, 0;\n\t"
        "tcgen05.mma.cta_group::1.kind::tf32 [%0], %1, %2, %3, p;\n\t}"
        :: "r"(d), "l"(ad), "l"(bd), "r"(IDESC_TF32), "r"(acc) : "memory");
}
__device__ __forceinline__ void mma_f16(uint32_t d, uint64_t ad, uint64_t bd, uint32_t acc) {
    asm volatile(
        "{\n\t.reg .pred p;\n\tsetp.ne.u32 p, %5, 0;\n\t"
        "tcgen05.mma.cta_group::1.kind::f16 [%0], %1, %2, %3, {%4, %4, %4, %4}, p;\n\t}"
        :: "r"(d), "l"(ad), "l"(bd), "r"(IDESC_F16), "r"(0u), "r"(acc) : "memory");
}

#define LDX32(r, a) \
    asm volatile( \
        "tcgen05.ld.sync.aligned.32x32b.x32.b32 " \
        "{%0, %1, %2, %3, %4, %5, %6, %7, %8, %9, %10, %11, %12, %13, %14, %15, " \
        " %16, %17, %18, %19, %20, %21, %22, %23, %24, %25, %26, %27, %28, %29, %30, %31}, [%32];" \
        : "=r"((r)[0]),  "=r"((r)[1]),  "=r"((r)[2]),  "=r"((r)[3]), \
          "=r"((r)[4]),  "=r"((r)[5]),  "=r"((r)[6]),  "=r"((r)[7]), \
          "=r"((r)[8]),  "=r"((r)[9]),  "=r"((r)[10]), "=r"((r)[11]), \
          "=r"((r)[12]), "=r"((r)[13]), "=r"((r)[14]), "=r"((r)[15]), \
          "=r"((r)[16]), "=r"((r)[17]), "=r"((r)[18]), "=r"((r)[19]), \
          "=r"((r)[20]), "=r"((r)[21]), "=r"((r)[22]), "=r"((r)[23]), \
          "=r"((r)[24]), "=r"((r)[25]), "=r"((r)[26]), "=r"((r)[27]), \
          "=r"((r)[28]), "=r"((r)[29]), "=r"((r)[30]), "=r"((r)[31]) \
        : "r"(a))
#endif

// ---------------------------------------------------------------------------
__global__ __launch_bounds__(256) void k_prep(const float* __restrict__ W1,
                                              const float* __restrict__ W2) {
    const int t = threadIdx.x, bx = blockIdx.x;     // grid 256
    if (bx < 16) g_colsum[bx * 256 + t] = 0.f;
    if (bx < F_) g_WT1[t * F_ + bx] = W1[bx * 256 + t];
    g_WT2h[t * HD + bx] = __float2half(W2[bx * 256 + t]);
}

// ---------------------------------------------------------------------------
// Small GEMM (tf32): P1h^T = (X @ W1)^T, output fp16
// ---------------------------------------------------------------------------
__global__ __launch_bounds__(128, 1)
void k_small_gemm(const __grid_constant__ CUtensorMap mapIn,
                  const __grid_constant__ CUtensorMap mapW,
                  const float* __restrict__ In) {
    const int tid = threadIdx.x, b = blockIdx.y, m0 = blockIdx.x * 128;
    __half* PTb = g_P1h + (size_t)b * HD * N_;
#if TC_OK
    constexpr int STG = 48 * 1024;
    extern __shared__ char dyn[];
    const uint32_t sbase = (smem_u32(dyn) + 1023) & ~1023u;
    __shared__ __align__(8) uint64_t s_bar[3];
    __shared__ uint32_t s_tmem[1];
    const int wid = tid >> 5, lane = tid & 31;
    const uint32_t bar0 = smem_u32(s_bar);

    if (tid == 0) for (int i = 0; i < 3; i++) MBAR_INIT(bar0 + i * 8, 1);
    if (wid == 0) { TC_ALLOC(smem_u32(s_tmem), 256); TC_RELINQ(); }
    __syncthreads();
    uint32_t tmem;
    asm volatile("ld.shared.b32 %0, [%1];" : "=r"(tmem) : "r"(smem_u32(s_tmem)));

    if (tid == 0) {
        const int yA = b * N_ + m0;
        for (int t = 0; t < 2; t++) {
            uint32_t sa = sbase + t * STG;
            MBAR_EXPECT_TX(bar0 + t * 8, STG);
            tma2d(sa,             &mapIn, t * 32, yA, bar0 + t * 8);
            tma2d(sa + 16 * 1024, &mapW,  t * 32, 0,  bar0 + t * 8);
        }
        for (int t = 0; t < 2; t++) {
            mbar_wait(bar0 + t * 8, 0);
            uint64_t a0 = sdesc(sbase + t * STG), b0 = sdesc(sbase + t * STG + 16 * 1024);
#pragma unroll
            for (int ks = 0; ks < 4; ks++)
                mma_tf32(tmem, a0 + ks * 2, b0 + ks * 2, (t > 0 || ks > 0) ? 1u : 0u);
        }
        TC_COMMIT(bar0 + 16);
    }
    mbar_wait(bar0 + 16, 0);
    TC_FENCE_AFTER();
    const int row = m0 + wid * 32 + lane;
#pragma unroll
    for (int c8 = 0; c8 < 8; c8++) {
        uint32_t r[32];
        LDX32(r, tmem + c8 * 32); TC_WAIT_LD();
#pragma unroll
        for (int j = 0; j < 32; j++)
            PTb[(size_t)(c8 * 32 + j) * N_ + row] = __float2half(__uint_as_float(r[j]));
    }
    __syncthreads();
    if (wid == 0) TC_DEALLOC(tmem, 256);
#else
    for (int idx = tid; idx < 128 * 256; idx += 128) {
        int m = idx >> 8, c = idx & 255;
        float acc = 0.f;
        const float* Inb = In + (size_t)b * N_ * F_ + (size_t)(m0 + m) * F_;
        for (int k = 0; k < F_; k++) acc += Inb[k] * g_WT1[(size_t)c * F_ + k];
        PTb[(size_t)c * N_ + m0 + m] = __float2half(acc);
    }
#endif
}

// ---------------------------------------------------------------------------
// Fused layer-1: A fp32 TMA -> smem; 127 threads convert -> SW64 fp16 ring
// (MMA operand) AND stream to g_Ah for big2. f16 MMA, k=32 chunks, NK=64.
// Epilogue: y = relu(LN(D+b1)); P2h = (y @ W2)^T (f16 GEMM).
// ---------------------------------------------------------------------------
__global__ __launch_bounds__(128, 1)
void k_fused1(const __grid_constant__ CUtensorMap mapA32,
              const __grid_constant__ CUtensorMap mapPh,
              const __grid_constant__ CUtensorMap mapW2h,
              const float* __restrict__ A,
              const float* __restrict__ bias, const float* __restrict__ gamma,
              const float* __restrict__ beta) {
    extern __shared__ char dyn[];
    const int tid = threadIdx.x, b = blockIdx.y, m0 = blockIdx.x * 256;
#if TC_OK
    constexpr int NK = 64;
    constexpr int A32OFF = 0;           // 3 x 32KB
    constexpr int POFF   = 96 * 1024;   // 3 x 16KB
    constexpr int A16OFF = 144 * 1024;  // 3 x 16KB
    constexpr int W2OFF  = 64 * 1024;   // epilogue (after drain)
    const uint32_t sbase = (smem_u32(dyn) + 1023) & ~1023u;
    const uint32_t abase = sbase - smem_u32(dyn);
    __shared__ __align__(8) uint64_t s_bar[11];
    __shared__ uint32_t s_tmem[1];
    __shared__ float sb[256], sg[256], st[256];
    const int wid = tid >> 5, lane = tid & 31;
    const uint32_t bar0 = smem_u32(s_bar);
    // bars: full[3]=+0, empty[3]=+24, final=+48, ef[2]=+56, ee=+72, efin=+80

    if (tid == 0) for (int i = 0; i < 11; i++) MBAR_INIT(bar0 + i * 8, 1);
    if (wid == 0) { TC_ALLOC(smem_u32(s_tmem), 512); TC_RELINQ(); }
    __syncthreads();
    uint32_t tmem;
    asm volatile("ld.shared.b32 %0, [%1];" : "=r"(tmem) : "r"(smem_u32(s_tmem)));

    if (tid != 0)
        for (int i = tid - 1; i < 256; i += 127) {
            sb[i] = bias[i]; sg[i] = gamma[i]; st[i] = beta[i];
        }
    __syncthreads();

    const int yA = b * N_ + m0, yB = b * HD;
    auto issue = [&](int t) {
        int s = t % 3;
        MBAR_EXPECT_TX(bar0 + s * 8, 49152);
        tma2d(sbase + A32OFF + s * 32768, &mapA32, t * 32, yA, bar0 + s * 8);
        tma2d(sbase + POFF   + s * 16384, &mapPh,  t * 32, yB, bar0 + s * 8);
    };
    if (tid == 0) { issue(0); issue(1); issue(2); }

    int fp[3] = {0, 0, 0}, ep[3] = {0, 0, 0};
    __half* AhB = g_Ah + (size_t)b * N_ * N_ + (size_t)m0 * N_;
#pragma unroll 1
    for (int t = 0; t < NK; t++) {
        int s = t % 3;
        mbar_wait(bar0 + s * 8, fp[s]); fp[s] ^= 1;    // all threads
        if (tid != 0) {
            // convert A32[s] (256 rows x 32 f) -> A16[s] SW64 (+ stream to g_Ah)
            const float4* src = (const float4*)(dyn + abase + A32OFF + s * 32768);
            char* d16 = dyn + abase + A16OFF + s * 16384;
            const int k0 = t * 32;
#pragma unroll 1
            for (int i = tid - 1; i < 2048; i += 127) {
                int r = i >> 3, c4 = i & 7;
                float4 v = src[i];
                h4 h;
                h.a = __floats2half2_rn(v.x, v.y);
                h.b = __floats2half2_rn(v.z, v.w);
                int half_t = r >> 7, rl = r & 127;
                *(h4*)(d16 + (half_t << 13) + SWZ64(rl * 64 + c4 * 8)) = h;
                *(h4*)(AhB + (size_t)r * N_ + k0 + c4 * 4) = h;
            }
            TC_FENCE_BEFORE();
            FENCE_ASYNC();
        }
        __syncthreads();
        if (tid == 0) {
            uint64_t a0 = sdesc64(sbase + A16OFF + s * 16384);
            uint64_t a1 = sdesc64(sbase + A16OFF + s * 16384 + 8192);
            uint64_t b0 = sdesc64(sbase + POFF + s * 16384);
#pragma unroll
            for (int ks = 0; ks < 2; ks++) {
                uint32_t acc = (t > 0 || ks > 0) ? 1u : 0u;
                mma_f16(tmem,       a0 + ks * 2, b0 + ks * 2, acc);
                mma_f16(tmem + 256, a1 + ks * 2, b0 + ks * 2, acc);
            }
            TC_COMMIT(bar0 + 24 + s * 8);
            int tn = t + 3;
            if (tn < NK) { mbar_wait(bar0 + 24 + s * 8, ep[s]); ep[s] ^= 1; issue(tn); }
        }
    }
    if (tid == 0) TC_COMMIT(bar0 + 48);
    mbar_wait(bar0 + 48, 0);
    __syncthreads();
    TC_FENCE_AFTER();

    // ---- epilogue: LN+ReLU; f16 GEMM P2 = y @ W2 ----
    int efp[2] = {0, 0}, eep = 0;
    auto issueW2 = [&](int chunk, int s) {      // chunk 0..3, each k=64
        MBAR_EXPECT_TX(bar0 + 56 + s * 8, 32768);
        tma2d(sbase + W2OFF + s * 32768, &mapW2h, chunk * 64, 0, bar0 + 56 + s * 8);
    };
    if (tid == 0) { issueW2(0, 0); issueW2(1, 1); }

#pragma unroll 1
    for (int half = 0; half < 2; half++) {
        const int row = wid * 32 + lane;
        const uint32_t dbase = tmem + half * 256;
        float sum = 0.f, sq = 0.f;
#pragma unroll 1
        for (int c8 = 0; c8 < 8; c8++) {
            uint32_t r[32];
            LDX32(r, dbase + c8 * 32); TC_WAIT_LD();
#pragma unroll
            for (int j = 0; j < 32; j++) {
                float v = __uint_as_float(r[j]) + sb[c8 * 32 + j];
                sum += v; sq += v * v;
            }
        }
        const float mu = sum * (1.f / HD);
        const float rs = rsqrtf(sq * (1.f / HD) - mu * mu + LN_EPS);

#pragma unroll 1
        for (int c8 = 0; c8 < 8; c8++) {
            uint32_t r[32];
            LDX32(r, dbase + c8 * 32); TC_WAIT_LD();
            float y[32];
#pragma unroll
            for (int j = 0; j < 32; j++) {
                float v = __uint_as_float(r[j]) + sb[c8 * 32 + j];
                y[j] = fmaxf((v - mu) * rs * sg[c8 * 32 + j] + st[c8 * 32 + j], 0.f);
            }
            char* ybase = dyn + abase + (c8 >> 1) * 16384;
            const int off = (c8 & 1) * 64;
#pragma unroll
            for (int q = 0; q < 4; q++) {
                __half2 h[4];
#pragma unroll
                for (int p = 0; p < 4; p++)
                    h[p] = __floats2half2_rn(y[q * 8 + 2 * p], y[q * 8 + 2 * p + 1]);
                *(float4*)(ybase + SWZ(row * 128 + off + q * 16)) = *(float4*)h;
            }
        }
        TC_FENCE_BEFORE();
        FENCE_ASYNC();
        __syncthreads();

        if (tid == 0) {
#pragma unroll 1
            for (int c = 0; c < 4; c++) {
                int s = c & 1;
                mbar_wait(bar0 + 56 + s * 8, efp[s]); efp[s] ^= 1;
                uint64_t yd = sdesc(sbase + c * 16384);
                uint64_t wd = sdesc(sbase + W2OFF + s * 32768);
#pragma unroll
                for (int ks = 0; ks < 4; ks++)
                    mma_f16(tmem + half * 256, yd + ks * 2, wd + ks * 2,
                            (c > 0 || ks > 0) ? 1u : 0u);
                TC_COMMIT(bar0 + 72);
                mbar_wait(bar0 + 72, eep & 1); eep++;
                int nxt = c + 2;
                if (nxt < 4)        issueW2(nxt, s);
                else if (half == 0) issueW2(nxt - 4, s);
            }
            TC_COMMIT(bar0 + 80);
        }
        mbar_wait(bar0 + 80, half);
        TC_FENCE_AFTER();

        __half* PTb = g_P2h + (size_t)b * HD * N_;
        const int grow = m0 + half * 128 + row;
#pragma unroll 1
        for (int c8 = 0; c8 < 8; c8++) {
            uint32_t r[32];
            LDX32(r, dbase + c8 * 32); TC_WAIT_LD();
#pragma unroll
            for (int j = 0; j < 32; j++)
                PTb[(size_t)(c8 * 32 + j) * N_ + grow] = __float2half(__uint_as_float(r[j]));
        }
        TC_FENCE_BEFORE();
        __syncthreads();
    }
    if (wid == 0) TC_DEALLOC(tmem, 512);
#else
    const float* Ab = A + (size_t)b * N_ * N_ + (size_t)m0 * N_;
    const __half* Bb = g_P1h + (size_t)b * HD * N_;
    __half* PTb = g_P2h + (size_t)b * HD * N_;
    __shared__ float arow[N_];
    __shared__ float drow[256];
    __shared__ float red[2][4];
    const int lane = tid & 31, wid = tid >> 5;
    for (int m = 0; m < 256; m++) {
        for (int i = tid; i < N_ / 4; i += 128)
            ((float4*)arow)[i] = ((const float4*)(Ab + (size_t)m * N_))[i];
        __syncthreads();
        for (int cp = 0; cp < 2; cp++) {
            int c = tid + cp * 128;
            float acc = 0.f;
            const __half* Brow = Bb + (size_t)c * N_;
            for (int k = 0; k < N_; k++) acc += arow[k] * __half2float(Brow[k]);
            drow[c] = acc + bias[c];
        }
        __syncthreads();
        float v0 = drow[tid], v1 = drow[tid + 128];
        float s = v0 + v1, q = v0 * v0 + v1 * v1;
        for (int o = 16; o > 0; o >>= 1) {
            s += __shfl_xor_sync(0xffffffff, s, o);
            q += __shfl_xor_sync(0xffffffff, q, o);
        }
        if (lane == 0) { red[0][wid] = s; red[1][wid] = q; }
        __syncthreads();
        float ts = red[0][0] + red[0][1] + red[0][2] + red[0][3];
        float tq = red[1][0] + red[1][1] + red[1][2] + red[1][3];
        float mu = ts * (1.f / HD);
        float rsv = rsqrtf(tq * (1.f / HD) - mu * mu + LN_EPS);
        drow[tid]       = fmaxf((v0 - mu) * rsv * gamma[tid] + beta[tid], 0.f);
        drow[tid + 128] = fmaxf((v1 - mu) * rsv * gamma[tid + 128] + beta[tid + 128], 0.f);
        __syncthreads();
        for (int cp = 0; cp < 2; cp++) {
            int c = tid + cp * 128;
            float acc = 0.f;
            for (int k = 0; k < HD; k++)
                acc += drow[k] * __half2float(g_WT2h[(size_t)c * HD + k]);
            PTb[(size_t)c * N_ + m0 + m] = __float2half(acc);
        }
        __syncthreads();
    }
#endif
}

// ---------------------------------------------------------------------------
// Layer-2 big GEMM (FP16): colsum += relu(LN(A_h @ P2h^T + b2))
// ---------------------------------------------------------------------------
__global__ __launch_bounds__(128, 1)
void k_big2(const __grid_constant__ CUtensorMap mapAh,
            const __grid_constant__ CUtensorMap mapPh,
            const float* __restrict__ A,
            const float* __restrict__ bias, const float* __restrict__ gamma,
            const float* __restrict__ beta) {
    extern __shared__ char dyn[];
    const int tid = threadIdx.x, b = blockIdx.y, m0 = blockIdx.x * 256;
#if TC_OK
    constexpr int NK = 32, STG = 64 * 1024;
    const uint32_t sbase = (smem_u32(dyn) + 1023) & ~1023u;
    __shared__ __align__(8) uint64_t s_bar[7];
    __shared__ uint32_t s_tmem[1];
    __shared__ float sb[256], sg[256], st[256];
    const int wid = tid >> 5, lane = tid & 31;
    const uint32_t bar0 = smem_u32(s_bar);

    if (tid == 0) for (int i = 0; i < 7; i++) MBAR_INIT(bar0 + i * 8, 1);
    if (wid == 0) { TC_ALLOC(smem_u32(s_tmem), 512); TC_RELINQ(); }
    __syncthreads();
    uint32_t tmem;
    asm volatile("ld.shared.b32 %0, [%1];" : "=r"(tmem) : "r"(smem_u32(s_tmem)));

    if (tid != 0)
        for (int i = tid - 1; i < 256; i += 127) {
            sb[i] = bias[i]; sg[i] = gamma[i]; st[i] = beta[i];
        }

    if (tid == 0) {
        int fp[3] = {0, 0, 0}, ep[3] = {0, 0, 0};
        const int yA = b * N_ + m0, yB = b * HD;
        auto issue = [&](int t) {
            int s = t % 3;
            uint32_t sa = sbase + s * STG;
            MBAR_EXPECT_TX(bar0 + s * 8, STG);
            tma2d(sa,             &mapAh, t * 64, yA, bar0 + s * 8);
            tma2d(sa + 32 * 1024, &mapPh, t * 64, yB, bar0 + s * 8);
        };
        issue(0); issue(1); issue(2);
#pragma unroll 1
        for (int t = 0; t < NK; t++) {
            int s = t % 3;
            mbar_wait(bar0 + s * 8, fp[s]); fp[s] ^= 1;
            uint64_t a0 = sdesc(sbase + s * STG);
            uint64_t a1 = sdesc(sbase + s * STG + 16 * 1024);
            uint64_t b0 = sdesc(sbase + s * STG + 32 * 1024);
#pragma unroll
            for (int ks = 0; ks < 4; ks++) {
                uint32_t acc = (t > 0 || ks > 0) ? 1u : 0u;
                mma_f16(tmem,       a0 + ks * 2, b0 + ks * 2, acc);
                mma_f16(tmem + 256, a1 + ks * 2, b0 + ks * 2, acc);
            }
            TC_COMMIT(bar0 + 24 + s * 8);
            int tn = t + 3;
            if (tn < NK) { mbar_wait(bar0 + 24 + s * 8, ep[s]); ep[s] ^= 1; issue(tn); }
        }
        TC_COMMIT(bar0 + 48);
    }
    mbar_wait(bar0 + 48, 0);
    TC_FENCE_AFTER();

    float* wsc = (float*)(dyn) + wid * 33 * 32;
#pragma unroll 1
    for (int half = 0; half < 2; half++) {
        const uint32_t dbase = tmem + half * 256;
        float sum = 0.f, sq = 0.f;
#pragma unroll 1
        for (int c8 = 0; c8 < 8; c8++) {
            uint32_t r[32];
            LDX32(r, dbase + c8 * 32); TC_WAIT_LD();
#pragma unroll
            for (int j = 0; j < 32; j++) {
                float v = __uint_as_float(r[j]) + sb[c8 * 32 + j];
                sum += v; sq += v * v;
            }
        }
        const float mu = sum * (1.f / HD);
        const float rs = rsqrtf(sq * (1.f / HD) - mu * mu + LN_EPS);
#pragma unroll 1
        for (int c8 = 0; c8 < 8; c8++) {
            uint32_t r[32];
            LDX32(r, dbase + c8 * 32); TC_WAIT_LD();
#pragma unroll
            for (int j = 0; j < 32; j++) {
                float v = __uint_as_float(r[j]) + sb[c8 * 32 + j];
                wsc[lane * 33 + j] =
                    fmaxf((v - mu) * rs * sg[c8 * 32 + j] + st[c8 * 32 + j], 0.f);
            }
            __syncwarp();
            float s2 = 0.f;
#pragma unroll
            for (int r2 = 0; r2 < 32; r2++) s2 += wsc[r2 * 33 + lane];
            atomicAdd(&g_colsum[b * HD + c8 * 32 + lane], s2);
            __syncwarp();
        }
    }
    __syncthreads();
    if (wid == 0) TC_DEALLOC(tmem, 512);
#else
    const float* Ab = A + (size_t)b * N_ * N_ + (size_t)m0 * N_;
    const __half* Bb = g_P2h + (size_t)b * HD * N_;
    __shared__ float arow[N_];
    __shared__ float drow[256];
    __shared__ float red[2][4];
    const int lane = tid & 31, wid = tid >> 5;
    float csum0 = 0.f, csum1 = 0.f;
    for (int m = 0; m < 256; m++) {
        for (int i = tid; i < N_ / 4; i += 128)
            ((float4*)arow)[i] = ((const float4*)(Ab + (size_t)m * N_))[i];
        __syncthreads();
        for (int cp = 0; cp < 2; cp++) {
            int c = tid + cp * 128;
            float acc = 0.f;
            const __half* Brow = Bb + (size_t)c * N_;
            for (int k = 0; k < N_; k++) acc += arow[k] * __half2float(Brow[k]);
            drow[c] = acc + bias[c];
        }
        __syncthreads();
        float v0 = drow[tid], v1 = drow[tid + 128];
        float s = v0 + v1, q = v0 * v0 + v1 * v1;
        for (int o = 16; o > 0; o >>= 1) {
            s += __shfl_xor_sync(0xffffffff, s, o);
            q += __shfl_xor_sync(0xffffffff, q, o);
        }
        if (lane == 0) { red[0][wid] = s; red[1][wid] = q; }
        __syncthreads();
        float ts = red[0][0] + red[0][1] + red[0][2] + red[0][3];
        float tq = red[1][0] + red[1][1] + red[1][2] + red[1][3];
        float mu = ts * (1.f / HD);
        float rsv = rsqrtf(tq * (1.f / HD) - mu * mu + LN_EPS);
        csum0 += fmaxf((v0 - mu) * rsv * gamma[tid] + beta[tid], 0.f);
        csum1 += fmaxf((v1 - mu) * rsv * gamma[tid + 128] + beta[tid + 128], 0.f);
        __syncthreads();
    }
    atomicAdd(&g_colsum[b * HD + tid], csum0);
    atomicAdd(&g_colsum[b * HD + tid + 128], csum1);
#endif
}

// ---------------------------------------------------------------------------
__global__ __launch_bounds__(288)
void k_finalize(const float* __restrict__ gvec,
                const float* __restrict__ Ws, const float* __restrict__ bs,
                const float* __restrict__ Wa, const float* __restrict__ ba,
                float* __restrict__ out) {
    __shared__ float fused[FUSE];
    const int b = blockIdx.x, t = threadIdx.x;
    if (t < HD)        fused[t] = g_colsum[b * HD + t] * (1.f / N_);
    else if (t < FUSE) fused[t] = gvec[b * GD + (t - HD)];
    __syncthreads();
    if (t < KD) {
        float a = ba[t];
        for (int i = 0; i < FUSE; i++) a += fused[i] * Wa[i * KD + t];
        out[B_ + b * KD + t] = a;
    } else if (t == KD) {
        float a = bs[0];
        for (int i = 0; i < FUSE; i++) a += fused[i] * Ws[i];
        out[b] = a;
    }
}

// ---------------------------------------------------------------------------
typedef CUresult (CUDAAPI *tmap_enc_t)(
    CUtensorMap*, CUtensorMapDataType, cuuint32_t, void*,
    const cuuint64_t*, const cuuint64_t*, const cuuint32_t*, const cuuint32_t*,
    CUtensorMapInterleave, CUtensorMapSwizzle, CUtensorMapL2promotion,
    CUtensorMapFloatOOBfill);

static void make_map(tmap_enc_t enc, CUtensorMap* m, const void* ptr,
                     CUtensorMapDataType dt, CUtensorMapSwizzle sw,
                     uint64_t d0, uint64_t d1, uint64_t stride1_bytes,
                     uint32_t box0, uint32_t box1) {
    cuuint64_t dims[2]    = {d0, d1};
    cuuint64_t strides[1] = {stride1_bytes};
    cuuint32_t box[2]     = {box0, box1};
    cuuint32_t es[2]      = {1, 1};
    enc(m, dt, 2, (void*)ptr, dims, strides, box, es,
        CU_TENSOR_MAP_INTERLEAVE_NONE, sw,
        CU_TENSOR_MAP_L2_PROMOTION_L2_128B, CU_TENSOR_MAP_FLOAT_OOB_FILL_NONE);
}

extern "C" void kernel_launch(void* const* d_in, const int* in_sizes, int n_in,
                              void* d_out, int out_size) {
    const float* A    = (const float*)d_in[0];
    const float* X    = (const float*)d_in[1];
    const float* gvec = (const float*)d_in[2];
    const float* W1   = (const float*)d_in[3];
    const float* b1   = (const float*)d_in[4];
    const float* g1   = (const float*)d_in[5];
    const float* be1  = (const float*)d_in[6];
    const float* W2   = (const float*)d_in[7];
    const float* b2   = (const float*)d_in[8];
    const float* g2   = (const float*)d_in[9];
    const float* be2  = (const float*)d_in[10];
    const float* Ws   = (const float*)d_in[11];
    const float* bs   = (const float*)d_in[12];
    const float* Wa   = (const float*)d_in[13];
    const float* ba   = (const float*)d_in[14];
    float* out = (float*)d_out;

    const int SMALL_SMEM = 2 * 48 * 1024 + 1024;
    const int F1_SMEM    = 192 * 1024 + 1024;
    const int BIG_SMEM   = 3 * 64 * 1024 + 1024;
    cudaFuncSetAttribute(k_small_gemm, cudaFuncAttributeMaxDynamicSharedMemorySize, SMALL_SMEM);
    cudaFuncSetAttribute(k_fused1,     cudaFuncAttributeMaxDynamicSharedMemorySize, F1_SMEM);
    cudaFuncSetAttribute(k_big2,       cudaFuncAttributeMaxDynamicSharedMemorySize, BIG_SMEM);

    float* WT1;
    __half *P1hp, *P2hp, *Ahp, *W2hp;
    cudaGetSymbolAddress((void**)&WT1,  g_WT1);
    cudaGetSymbolAddress((void**)&P1hp, g_P1h);
    cudaGetSymbolAddress((void**)&P2hp, g_P2h);
    cudaGetSymbolAddress((void**)&Ahp,  g_Ah);
    cudaGetSymbolAddress((void**)&W2hp, g_WT2h);

    tmap_enc_t enc = nullptr;
#if CUDART_VERSION >= 12050
    cudaDriverEntryPointQueryResult qr;
    cudaGetDriverEntryPointByVersion("cuTensorMapEncodeTiled", (void**)&enc, 12000,
                                     cudaEnableDefault, &qr);
#else
    cudaGetDriverEntryPoint("cuTensorMapEncodeTiled", (void**)&enc, cudaEnableDefault);
#endif

    CUtensorMap mX, mW1, mA32, mP1h64, mAh, mP2h, mW2h;
    make_map(enc, &mX,     X,    CU_TENSOR_MAP_DATA_TYPE_FLOAT32, CU_TENSOR_MAP_SWIZZLE_128B,
             F_, (uint64_t)N_ * B_, (uint64_t)F_ * 4, 32, 128);
    make_map(enc, &mW1,    WT1,  CU_TENSOR_MAP_DATA_TYPE_FLOAT32, CU_TENSOR_MAP_SWIZZLE_128B,
             F_, HD, (uint64_t)F_ * 4, 32, 256);
    make_map(enc, &mA32,   A,    CU_TENSOR_MAP_DATA_TYPE_FLOAT32, CU_TENSOR_MAP_SWIZZLE_NONE,
             N_, (uint64_t)N_ * B_, (uint64_t)N_ * 4, 32, 256);
    make_map(enc, &mP1h64, P1hp, CU_TENSOR_MAP_DATA_TYPE_FLOAT16, CU_TENSOR_MAP_SWIZZLE_64B,
             N_, (uint64_t)HD * B_, (uint64_t)N_ * 2, 32, 256);
    make_map(enc, &mAh,    Ahp,  CU_TENSOR_MAP_DATA_TYPE_FLOAT16, CU_TENSOR_MAP_SWIZZLE_128B,
             N_, (uint64_t)N_ * B_, (uint64_t)N_ * 2, 64, 256);
    make_map(enc, &mP2h,   P2hp, CU_TENSOR_MAP_DATA_TYPE_FLOAT16, CU_TENSOR_MAP_SWIZZLE_128B,
             N_, (uint64_t)HD * B_, (uint64_t)N_ * 2, 64, 256);
    make_map(enc, &mW2h,   W2hp, CU_TENSOR_MAP_DATA_TYPE_FLOAT16, CU_TENSOR_MAP_SWIZZLE_128B,
             HD, HD, (uint64_t)HD * 2, 64, 256);

    k_prep<<<256, 256>>>(W1, W2);
    k_small_gemm<<<dim3(N_ / 128, B_), 128, SMALL_SMEM>>>(mX, mW1, X);
    k_fused1<<<dim3(N_ / 256, B_), 128, F1_SMEM>>>(mA32, mP1h64, mW2h, A, b1, g1, be1);
    k_big2<<<dim3(N_ / 256, B_), 128, BIG_SMEM>>>(mAh, mP2h, A, b2, g2, be2);
    k_finalize<<<B_, 288>>>(gvec, Ws, bs, Wa, ba, out);
}

// round 13
// speedup vs baseline: 1.0893x; 1.0809x over previous
#include <cuda_runtime.h>
#include <cuda.h>
#include <cuda_fp16.h>
#include <cstdint>
#include <math.h>

#define B_   16
#define N_   2048
#define F_   64
#define HD   256
#define GD   18
#define KD   128
#define FUSE 274
#define LN_EPS 1e-5f

#if defined(__CUDA_ARCH_FEAT_SM103_ALL) || defined(__CUDA_ARCH_FEAT_SM100_ALL) || \
    defined(__CUDA_ARCH_FEAT_SM101_ALL) || \
    (defined(__CUDA_ARCH_SPECIFIC__) && (__CUDA_ARCH_SPECIFIC__ >= 1000)) || \
    (defined(__CUDA_ARCH_FAMILY_SPECIFIC__) && (__CUDA_ARCH_FAMILY_SPECIFIC__ >= 1000))
#define TC_OK 1
#else
#define TC_OK 0
#endif

__device__ __align__(1024) __half g_P1h[B_ * HD * N_];
__device__ __align__(1024) __half g_P2h[B_ * HD * N_];
__device__ __align__(1024) __half g_Ah[(size_t)B_ * N_ * N_];
__device__ __align__(1024) float  g_WT1[HD * F_];
__device__ __align__(1024) __half g_WT2h[HD * HD];
__device__ float g_colsum[B_ * HD];

__device__ __forceinline__ uint32_t smem_u32(const void* p) {
    uint32_t a;
    asm("{ .reg .u64 t; cvta.to.shared.u64 t, %1; cvt.u32.u64 %0, t; }" : "=r"(a) : "l"(p));
    return a;
}
#define SWZ(x) ((x) ^ (((x) >> 3) & 0x70))
#define MBAR_INIT(a, c) \
    asm volatile("mbarrier.init.shared.b64 [%0], %1;" :: "r"(a), "r"(c) : "memory")
#define MBAR_EXPECT_TX(a, n) \
    asm volatile("mbarrier.arrive.expect_tx.shared.b64 _, [%0], %1;" :: "r"(a), "r"(n) : "memory")
#define FENCE_ASYNC() asm volatile("fence.proxy.async.shared::cta;" ::: "memory")

__device__ __forceinline__ void mbar_wait(uint32_t mbar, uint32_t parity) {
    asm volatile(
        "{\n\t.reg .pred P1;\n\t"
        "WL_%=:\n\t"
        "mbarrier.try_wait.parity.acquire.cta.shared::cta.b64 P1, [%0], %1, 0x989680;\n\t"
        "@P1 bra.uni WD_%=;\n\t"
        "bra.uni WL_%=;\n\t"
        "WD_%=:\n\t}"
        :: "r"(mbar), "r"(parity) : "memory");
}

#if TC_OK
__device__ __forceinline__ uint64_t sdesc(uint32_t addr) {
    return ((2ull << 61) | (1ull << 46) | (64ull << 32) | (1ull << 16))
         | ((uint64_t)(addr >> 4) & 0x3FFF);
}
__device__ __forceinline__ void tma2d(uint32_t dst, const CUtensorMap* m, int x, int y,
                                      uint32_t mbar) {
    asm volatile(
        "cp.async.bulk.tensor.2d.shared::cta.global.tile.mbarrier::complete_tx::bytes "
        "[%0], [%1, {%2, %3}], [%4];"
        :: "r"(dst), "l"(m), "r"(x), "r"(y), "r"(mbar) : "memory");
}
#define TC_COMMIT(a) \
    asm volatile("tcgen05.commit.cta_group::1.mbarrier::arrive::one.shared::cluster.b64 [%0];" \
                 :: "r"(a) : "memory")
#define TC_ALLOC(a, n) \
    asm volatile("tcgen05.alloc.cta_group::1.sync.aligned.shared::cta.b32 [%0], %1;" \
                 :: "r"(a), "r"(n) : "memory")
#define TC_RELINQ() \
    asm volatile("tcgen05.relinquish_alloc_permit.cta_group::1.sync.aligned;")
#define TC_DEALLOC(t, n) \
    asm volatile("tcgen05.dealloc.cta_group::1.sync.aligned.b32 %0, %1;" :: "r"(t), "r"(n))
#define TC_FENCE_AFTER()  asm volatile("tcgen05.fence::after_thread_sync;" ::: "memory")
#define TC_FENCE_BEFORE() asm volatile("tcgen05.fence::before_thread_sync;" ::: "memory")
#define TC_WAIT_LD() asm volatile("tcgen05.wait::ld.sync.aligned;" ::: "memory")

#define IDESC_TF32 ((1u << 4) | (2u << 7) | (2u << 10) | (32u << 17) | (8u << 24))
#define IDESC_F16  ((1u << 4) | (32u << 17) | (8u << 24))

__device__ __forceinline__ void mma_tf32(uint32_t d, uint64_t ad, uint64_t bd, uint32_t acc) {
    asm volatile(
        "{\n\t.reg .pred p;\n\tsetp.ne.u32 p, %4, 0;\n\t"
        "tcgen05.mma.cta_group::1.kind::tf32 [%0], %1, %2, %3, p;\n\t}"
        :: "r"(d), "l"(ad), "l"(bd), "r"(IDESC_TF32), "r"(acc) : "memory");
}
__device__ __forceinline__ void mma_f16(uint32_t d, uint64_t ad, uint64_t bd, uint32_t acc) {
    asm volatile(
        "{\n\t.reg .pred p;\n\tsetp.ne.u32 p, %5, 0;\n\t"
        "tcgen05.mma.cta_group::1.kind::f16 [%0], %1, %2, %3, {%4, %4, %4, %4}, p;\n\t}"
        :: "r"(d), "l"(ad), "l"(bd), "r"(IDESC_F16), "r"(0u), "r"(acc) : "memory");
}

#define LDX32(r, a) \
    asm volatile( \
        "tcgen05.ld.sync.aligned.32x32b.x32.b32 " \
        "{%0, %1, %2, %3, %4, %5, %6, %7, %8, %9, %10, %11, %12, %13, %14, %15, " \
        " %16, %17, %18, %19, %20, %21, %22, %23, %24, %25, %26, %27, %28, %29, %30, %31}, [%32];" \
        : "=r"((r)[0]),  "=r"((r)[1]),  "=r"((r)[2]),  "=r"((r)[3]), \
          "=r"((r)[4]),  "=r"((r)[5]),  "=r"((r)[6]),  "=r"((r)[7]), \
          "=r"((r)[8]),  "=r"((r)[9]),  "=r"((r)[10]), "=r"((r)[11]), \
          "=r"((r)[12]), "=r"((r)[13]), "=r"((r)[14]), "=r"((r)[15]), \
          "=r"((r)[16]), "=r"((r)[17]), "=r"((r)[18]), "=r"((r)[19]), \
          "=r"((r)[20]), "=r"((r)[21]), "=r"((r)[22]), "=r"((r)[23]), \
          "=r"((r)[24]), "=r"((r)[25]), "=r"((r)[26]), "=r"((r)[27]), \
          "=r"((r)[28]), "=r"((r)[29]), "=r"((r)[30]), "=r"((r)[31]) \
        : "r"(a))
#endif

// ---------------------------------------------------------------------------
__global__ __launch_bounds__(256) void k_prep(const float* __restrict__ W1,
                                              const float* __restrict__ W2) {
    const int t = threadIdx.x, bx = blockIdx.x;     // grid 256
    if (bx < 16) g_colsum[bx * 256 + t] = 0.f;
    if (bx < F_) g_WT1[t * F_ + bx] = W1[bx * 256 + t];
    g_WT2h[t * HD + bx] = __float2half(W2[bx * 256 + t]);
}

__global__ __launch_bounds__(256) void k_convA(const float* __restrict__ A) {
    const float4* src = (const float4*)A;
    __half2* dst = (__half2*)g_Ah;
    const size_t total = (size_t)B_ * N_ * N_ / 4;
    for (size_t i = (size_t)blockIdx.x * 256 + threadIdx.x; i < total;
         i += (size_t)gridDim.x * 256) {
        float4 v = src[i];
        dst[2 * i]     = __floats2half2_rn(v.x, v.y);
        dst[2 * i + 1] = __floats2half2_rn(v.z, v.w);
    }
}

// ---------------------------------------------------------------------------
// Small GEMM (tf32): P1h^T = (X @ W1)^T, output fp16
// ---------------------------------------------------------------------------
__global__ __launch_bounds__(128, 1)
void k_small_gemm(const __grid_constant__ CUtensorMap mapIn,
                  const __grid_constant__ CUtensorMap mapW,
                  const float* __restrict__ In) {
    const int tid = threadIdx.x, b = blockIdx.y, m0 = blockIdx.x * 128;
    __half* PTb = g_P1h + (size_t)b * HD * N_;
#if TC_OK
    constexpr int STG = 48 * 1024;
    extern __shared__ char dyn[];
    const uint32_t sbase = (smem_u32(dyn) + 1023) & ~1023u;
    __shared__ __align__(8) uint64_t s_bar[3];
    __shared__ uint32_t s_tmem[1];
    const int wid = tid >> 5, lane = tid & 31;
    const uint32_t bar0 = smem_u32(s_bar);

    if (tid == 0) for (int i = 0; i < 3; i++) MBAR_INIT(bar0 + i * 8, 1);
    if (wid == 0) { TC_ALLOC(smem_u32(s_tmem), 256); TC_RELINQ(); }
    __syncthreads();
    uint32_t tmem;
    asm volatile("ld.shared.b32 %0, [%1];" : "=r"(tmem) : "r"(smem_u32(s_tmem)));

    if (tid == 0) {
        const int yA = b * N_ + m0;
        for (int t = 0; t < 2; t++) {
            uint32_t sa = sbase + t * STG;
            MBAR_EXPECT_TX(bar0 + t * 8, STG);
            tma2d(sa,             &mapIn, t * 32, yA, bar0 + t * 8);
            tma2d(sa + 16 * 1024, &mapW,  t * 32, 0,  bar0 + t * 8);
        }
        for (int t = 0; t < 2; t++) {
            mbar_wait(bar0 + t * 8, 0);
            uint64_t a0 = sdesc(sbase + t * STG), b0 = sdesc(sbase + t * STG + 16 * 1024);
#pragma unroll
            for (int ks = 0; ks < 4; ks++)
                mma_tf32(tmem, a0 + ks * 2, b0 + ks * 2, (t > 0 || ks > 0) ? 1u : 0u);
        }
        TC_COMMIT(bar0 + 16);
    }
    mbar_wait(bar0 + 16, 0);
    TC_FENCE_AFTER();
    const int row = m0 + wid * 32 + lane;
#pragma unroll
    for (int c8 = 0; c8 < 8; c8++) {
        uint32_t r[32];
        LDX32(r, tmem + c8 * 32); TC_WAIT_LD();
#pragma unroll
        for (int j = 0; j < 32; j++)
            PTb[(size_t)(c8 * 32 + j) * N_ + row] = __float2half(__uint_as_float(r[j]));
    }
    __syncthreads();
    if (wid == 0) TC_DEALLOC(tmem, 256);
#else
    for (int idx = tid; idx < 128 * 256; idx += 128) {
        int m = idx >> 8, c = idx & 255;
        float acc = 0.f;
        const float* Inb = In + (size_t)b * N_ * F_ + (size_t)(m0 + m) * F_;
        for (int k = 0; k < F_; k++) acc += Inb[k] * g_WT1[(size_t)c * F_ + k];
        PTb[(size_t)c * N_ + m0 + m] = __float2half(acc);
    }
#endif
}

// ---------------------------------------------------------------------------
// Fused layer-1 (FP16 mainloop, lagged refill): D = A_h @ P1h^T^T ;
// y = relu(LN(D+b1)) ; P2h = (y @ W2)^T via f16 epilogue GEMM.
// ---------------------------------------------------------------------------
__global__ __launch_bounds__(128, 1)
void k_fused1(const __grid_constant__ CUtensorMap mapAh,
              const __grid_constant__ CUtensorMap mapPh,
              const __grid_constant__ CUtensorMap mapW2h,
              const float* __restrict__ A,
              const float* __restrict__ bias, const float* __restrict__ gamma,
              const float* __restrict__ beta) {
    extern __shared__ char dyn[];
    const int tid = threadIdx.x, b = blockIdx.y, m0 = blockIdx.x * 256;
#if TC_OK
    constexpr int NK = 32, STG = 64 * 1024, W2OFF = 64 * 1024;
    const uint32_t sbase = (smem_u32(dyn) + 1023) & ~1023u;
    const uint32_t abase = sbase - smem_u32(dyn);
    __shared__ __align__(8) uint64_t s_bar[11];
    __shared__ uint32_t s_tmem[1];
    __shared__ float sb[256], sg[256], st[256];
    const int wid = tid >> 5, lane = tid & 31;
    const uint32_t bar0 = smem_u32(s_bar);
    // bars: full[3]=+0, empty[3]=+24, final=+48, ef[2]=+56, ee=+72, efin=+80

    if (tid == 0) for (int i = 0; i < 11; i++) MBAR_INIT(bar0 + i * 8, 1);
    if (wid == 0) { TC_ALLOC(smem_u32(s_tmem), 512); TC_RELINQ(); }
    __syncthreads();
    uint32_t tmem;
    asm volatile("ld.shared.b32 %0, [%1];" : "=r"(tmem) : "r"(smem_u32(s_tmem)));

    if (tid != 0)
        for (int i = tid - 1; i < 256; i += 127) {
            sb[i] = bias[i]; sg[i] = gamma[i]; st[i] = beta[i];
        }

    if (tid == 0) {
        int fp[3] = {0, 0, 0}, ep[3] = {0, 0, 0};
        const int yA = b * N_ + m0, yB = b * HD;
        auto issue = [&](int t) {
            int s = t % 3;
            uint32_t sa = sbase + s * STG;
            MBAR_EXPECT_TX(bar0 + s * 8, STG);
            tma2d(sa,             &mapAh, t * 64, yA, bar0 + s * 8);
            tma2d(sa + 32 * 1024, &mapPh, t * 64, yB, bar0 + s * 8);
        };
        issue(0); issue(1); issue(2);
#pragma unroll 1
        for (int t = 0; t < NK; t++) {
            int s = t % 3;
            mbar_wait(bar0 + s * 8, fp[s]); fp[s] ^= 1;
            uint64_t a0 = sdesc(sbase + s * STG);
            uint64_t a1 = sdesc(sbase + s * STG + 16 * 1024);
            uint64_t b0 = sdesc(sbase + s * STG + 32 * 1024);
#pragma unroll
            for (int ks = 0; ks < 4; ks++) {
                uint32_t acc = (t > 0 || ks > 0) ? 1u : 0u;
                mma_f16(tmem,       a0 + ks * 2, b0 + ks * 2, acc);
                mma_f16(tmem + 256, a1 + ks * 2, b0 + ks * 2, acc);
            }
            TC_COMMIT(bar0 + 24 + s * 8);
            // lagged refill: chunk t+2 -> stage (t+2)%3, guarded by commit from
            // iteration t-1 (mostly drained -> wait is just wakeup latency)
            int tn = t + 2;
            if (t >= 1 && tn < NK) {
                int sp = tn % 3;
                mbar_wait(bar0 + 24 + sp * 8, ep[sp]); ep[sp] ^= 1;
                issue(tn);
            }
        }
        TC_COMMIT(bar0 + 48);
    }
    mbar_wait(bar0 + 48, 0);
    __syncthreads();
    TC_FENCE_AFTER();

    // ---- epilogue: y fp16 -> smem; f16 GEMM P2 = y @ W2 ----
    int efp[2] = {0, 0}, eep = 0;
    auto issueW2 = [&](int chunk, int s) {      // chunk 0..3, each k=64
        MBAR_EXPECT_TX(bar0 + 56 + s * 8, 32768);
        tma2d(sbase + W2OFF + s * 32768, &mapW2h, chunk * 64, 0, bar0 + 56 + s * 8);
    };
    if (tid == 0) { issueW2(0, 0); issueW2(1, 1); }

#pragma unroll 1
    for (int half = 0; half < 2; half++) {
        const int row = wid * 32 + lane;
        const uint32_t dbase = tmem + half * 256;
        float sum = 0.f, sq = 0.f;
#pragma unroll 1
        for (int c8 = 0; c8 < 8; c8++) {
            uint32_t r[32];
            LDX32(r, dbase + c8 * 32); TC_WAIT_LD();
#pragma unroll
            for (int j = 0; j < 32; j++) {
                float v = __uint_as_float(r[j]) + sb[c8 * 32 + j];
                sum += v; sq += v * v;
            }
        }
        const float mu = sum * (1.f / HD);
        const float rs = rsqrtf(sq * (1.f / HD) - mu * mu + LN_EPS);

#pragma unroll 1
        for (int c8 = 0; c8 < 8; c8++) {
            uint32_t r[32];
            LDX32(r, dbase + c8 * 32); TC_WAIT_LD();
            float y[32];
#pragma unroll
            for (int j = 0; j < 32; j++) {
                float v = __uint_as_float(r[j]) + sb[c8 * 32 + j];
                y[j] = fmaxf((v - mu) * rs * sg[c8 * 32 + j] + st[c8 * 32 + j], 0.f);
            }
            char* ybase = dyn + abase + (c8 >> 1) * 16384;
            const int off = (c8 & 1) * 64;
#pragma unroll
            for (int q = 0; q < 4; q++) {
                __half2 h[4];
#pragma unroll
                for (int p = 0; p < 4; p++)
                    h[p] = __floats2half2_rn(y[q * 8 + 2 * p], y[q * 8 + 2 * p + 1]);
                *(float4*)(ybase + SWZ(row * 128 + off + q * 16)) = *(float4*)h;
            }
        }
        TC_FENCE_BEFORE();
        FENCE_ASYNC();
        __syncthreads();

        if (tid == 0) {
#pragma unroll 1
            for (int c = 0; c < 4; c++) {
                int s = c & 1;
                mbar_wait(bar0 + 56 + s * 8, efp[s]); efp[s] ^= 1;
                uint64_t yd = sdesc(sbase + c * 16384);
                uint64_t wd = sdesc(sbase + W2OFF + s * 32768);
#pragma unroll
                for (int ks = 0; ks < 4; ks++)
                    mma_f16(tmem + half * 256, yd + ks * 2, wd + ks * 2,
                            (c > 0 || ks > 0) ? 1u : 0u);
                TC_COMMIT(bar0 + 72);
                mbar_wait(bar0 + 72, eep & 1); eep++;
                int nxt = c + 2;
                if (nxt < 4)        issueW2(nxt, s);
                else if (half == 0) issueW2(nxt - 4, s);
            }
            TC_COMMIT(bar0 + 80);
        }
        mbar_wait(bar0 + 80, half);
        TC_FENCE_AFTER();

        __half* PTb = g_P2h + (size_t)b * HD * N_;
        const int grow = m0 + half * 128 + row;
#pragma unroll 1
        for (int c8 = 0; c8 < 8; c8++) {
            uint32_t r[32];
            LDX32(r, dbase + c8 * 32); TC_WAIT_LD();
#pragma unroll
            for (int j = 0; j < 32; j++)
                PTb[(size_t)(c8 * 32 + j) * N_ + grow] = __float2half(__uint_as_float(r[j]));
        }
        TC_FENCE_BEFORE();
        __syncthreads();
    }
    if (wid == 0) TC_DEALLOC(tmem, 512);
#else
    const float* Ab = A + (size_t)b * N_ * N_ + (size_t)m0 * N_;
    const __half* Bb = g_P1h + (size_t)b * HD * N_;
    __half* PTb = g_P2h + (size_t)b * HD * N_;
    __shared__ float arow[N_];
    __shared__ float drow[256];
    __shared__ float red[2][4];
    const int lane = tid & 31, wid = tid >> 5;
    for (int m = 0; m < 256; m++) {
        for (int i = tid; i < N_ / 4; i += 128)
            ((float4*)arow)[i] = ((const float4*)(Ab + (size_t)m * N_))[i];
        __syncthreads();
        for (int cp = 0; cp < 2; cp++) {
            int c = tid + cp * 128;
            float acc = 0.f;
            const __half* Brow = Bb + (size_t)c * N_;
            for (int k = 0; k < N_; k++) acc += arow[k] * __half2float(Brow[k]);
            drow[c] = acc + bias[c];
        }
        __syncthreads();
        float v0 = drow[tid], v1 = drow[tid + 128];
        float s = v0 + v1, q = v0 * v0 + v1 * v1;
        for (int o = 16; o > 0; o >>= 1) {
            s += __shfl_xor_sync(0xffffffff, s, o);
            q += __shfl_xor_sync(0xffffffff, q, o);
        }
        if (lane == 0) { red[0][wid] = s; red[1][wid] = q; }
        __syncthreads();
        float ts = red[0][0] + red[0][1] + red[0][2] + red[0][3];
        float tq = red[1][0] + red[1][1] + red[1][2] + red[1][3];
        float mu = ts * (1.f / HD);
        float rsv = rsqrtf(tq * (1.f / HD) - mu * mu + LN_EPS);
        drow[tid]       = fmaxf((v0 - mu) * rsv * gamma[tid] + beta[tid], 0.f);
        drow[tid + 128] = fmaxf((v1 - mu) * rsv * gamma[tid + 128] + beta[tid + 128], 0.f);
        __syncthreads();
        for (int cp = 0; cp < 2; cp++) {
            int c = tid + cp * 128;
            float acc = 0.f;
            for (int k = 0; k < HD; k++)
                acc += drow[k] * __half2float(g_WT2h[(size_t)c * HD + k]);
            PTb[(size_t)c * N_ + m0 + m] = __float2half(acc);
        }
        __syncthreads();
    }
#endif
}

// ---------------------------------------------------------------------------
// Layer-2 big GEMM (FP16, lagged refill): colsum += relu(LN(A_h @ P2h^T + b2))
// ---------------------------------------------------------------------------
__global__ __launch_bounds__(128, 1)
void k_big2(const __grid_constant__ CUtensorMap mapAh,
            const __grid_constant__ CUtensorMap mapPh,
            const float* __restrict__ A,
            const float* __restrict__ bias, const float* __restrict__ gamma,
            const float* __restrict__ beta) {
    extern __shared__ char dyn[];
    const int tid = threadIdx.x, b = blockIdx.y, m0 = blockIdx.x * 256;
#if TC_OK
    constexpr int NK = 32, STG = 64 * 1024;
    const uint32_t sbase = (smem_u32(dyn) + 1023) & ~1023u;
    __shared__ __align__(8) uint64_t s_bar[7];
    __shared__ uint32_t s_tmem[1];
    __shared__ float sb[256], sg[256], st[256];
    const int wid = tid >> 5, lane = tid & 31;
    const uint32_t bar0 = smem_u32(s_bar);

    if (tid == 0) for (int i = 0; i < 7; i++) MBAR_INIT(bar0 + i * 8, 1);
    if (wid == 0) { TC_ALLOC(smem_u32(s_tmem), 512); TC_RELINQ(); }
    __syncthreads();
    uint32_t tmem;
    asm volatile("ld.shared.b32 %0, [%1];" : "=r"(tmem) : "r"(smem_u32(s_tmem)));

    if (tid != 0)
        for (int i = tid - 1; i < 256; i += 127) {
            sb[i] = bias[i]; sg[i] = gamma[i]; st[i] = beta[i];
        }

    if (tid == 0) {
        int fp[3] = {0, 0, 0}, ep[3] = {0, 0, 0};
        const int yA = b * N_ + m0, yB = b * HD;
        auto issue = [&](int t) {
            int s = t % 3;
            uint32_t sa = sbase + s * STG;
            MBAR_EXPECT_TX(bar0 + s * 8, STG);
            tma2d(sa,             &mapAh, t * 64, yA, bar0 + s * 8);
            tma2d(sa + 32 * 1024, &mapPh, t * 64, yB, bar0 + s * 8);
        };
        issue(0); issue(1); issue(2);
#pragma unroll 1
        for (int t = 0; t < NK; t++) {
            int s = t % 3;
            mbar_wait(bar0 + s * 8, fp[s]); fp[s] ^= 1;
            uint64_t a0 = sdesc(sbase + s * STG);
            uint64_t a1 = sdesc(sbase + s * STG + 16 * 1024);
            uint64_t b0 = sdesc(sbase + s * STG + 32 * 1024);
#pragma unroll
            for (int ks = 0; ks < 4; ks++) {
                uint32_t acc = (t > 0 || ks > 0) ? 1u : 0u;
                mma_f16(tmem,       a0 + ks * 2, b0 + ks * 2, acc);
                mma_f16(tmem + 256, a1 + ks * 2, b0 + ks * 2, acc);
            }
            TC_COMMIT(bar0 + 24 + s * 8);
            // lagged refill (see k_fused1)
            int tn = t + 2;
            if (t >= 1 && tn < NK) {
                int sp = tn % 3;
                mbar_wait(bar0 + 24 + sp * 8, ep[sp]); ep[sp] ^= 1;
                issue(tn);
            }
        }
        TC_COMMIT(bar0 + 48);
    }
    mbar_wait(bar0 + 48, 0);
    TC_FENCE_AFTER();

    float* wsc = (float*)(dyn) + wid * 33 * 32;
#pragma unroll 1
    for (int half = 0; half < 2; half++) {
        const uint32_t dbase = tmem + half * 256;
        float sum = 0.f, sq = 0.f;
#pragma unroll 1
        for (int c8 = 0; c8 < 8; c8++) {
            uint32_t r[32];
            LDX32(r, dbase + c8 * 32); TC_WAIT_LD();
#pragma unroll
            for (int j = 0; j < 32; j++) {
                float v = __uint_as_float(r[j]) + sb[c8 * 32 + j];
                sum += v; sq += v * v;
            }
        }
        const float mu = sum * (1.f / HD);
        const float rs = rsqrtf(sq * (1.f / HD) - mu * mu + LN_EPS);
#pragma unroll 1
        for (int c8 = 0; c8 < 8; c8++) {
            uint32_t r[32];
            LDX32(r, dbase + c8 * 32); TC_WAIT_LD();
#pragma unroll
            for (int j = 0; j < 32; j++) {
                float v = __uint_as_float(r[j]) + sb[c8 * 32 + j];
                wsc[lane * 33 + j] =
                    fmaxf((v - mu) * rs * sg[c8 * 32 + j] + st[c8 * 32 + j], 0.f);
            }
            __syncwarp();
            float s2 = 0.f;
#pragma unroll
            for (int r2 = 0; r2 < 32; r2++) s2 += wsc[r2 * 33 + lane];
            atomicAdd(&g_colsum[b * HD + c8 * 32 + lane], s2);
            __syncwarp();
        }
    }
    __syncthreads();
    if (wid == 0) TC_DEALLOC(tmem, 512);
#else
    const float* Ab = A + (size_t)b * N_ * N_ + (size_t)m0 * N_;
    const __half* Bb = g_P2h + (size_t)b * HD * N_;
    __shared__ float arow[N_];
    __shared__ float drow[256];
    __shared__ float red[2][4];
    const int lane = tid & 31, wid = tid >> 5;
    float csum0 = 0.f, csum1 = 0.f;
    for (int m = 0; m < 256; m++) {
        for (int i = tid; i < N_ / 4; i += 128)
            ((float4*)arow)[i] = ((const float4*)(Ab + (size_t)m * N_))[i];
        __syncthreads();
        for (int cp = 0; cp < 2; cp++) {
            int c = tid + cp * 128;
            float acc = 0.f;
            const __half* Brow = Bb + (size_t)c * N_;
            for (int k = 0; k < N_; k++) acc += arow[k] * __half2float(Brow[k]);
            drow[c] = acc + bias[c];
        }
        __syncthreads();
        float v0 = drow[tid], v1 = drow[tid + 128];
        float s = v0 + v1, q = v0 * v0 + v1 * v1;
        for (int o = 16; o > 0; o >>= 1) {
            s += __shfl_xor_sync(0xffffffff, s, o);
            q += __shfl_xor_sync(0xffffffff, q, o);
        }
        if (lane == 0) { red[0][wid] = s; red[1][wid] = q; }
        __syncthreads();
        float ts = red[0][0] + red[0][1] + red[0][2] + red[0][3];
        float tq = red[1][0] + red[1][1] + red[1][2] + red[1][3];
        float mu = ts * (1.f / HD);
        float rsv = rsqrtf(tq * (1.f / HD) - mu * mu + LN_EPS);
        csum0 += fmaxf((v0 - mu) * rsv * gamma[tid] + beta[tid], 0.f);
        csum1 += fmaxf((v1 - mu) * rsv * gamma[tid + 128] + beta[tid + 128], 0.f);
        __syncthreads();
    }
    atomicAdd(&g_colsum[b * HD + tid], csum0);
    atomicAdd(&g_colsum[b * HD + tid + 128], csum1);
#endif
}

// ---------------------------------------------------------------------------
__global__ __launch_bounds__(288)
void k_finalize(const float* __restrict__ gvec,
                const float* __restrict__ Ws, const float* __restrict__ bs,
                const float* __restrict__ Wa, const float* __restrict__ ba,
                float* __restrict__ out) {
    __shared__ float fused[FUSE];
    const int b = blockIdx.x, t = threadIdx.x;
    if (t < HD)        fused[t] = g_colsum[b * HD + t] * (1.f / N_);
    else if (t < FUSE) fused[t] = gvec[b * GD + (t - HD)];
    __syncthreads();
    if (t < KD) {
        float a = ba[t];
        for (int i = 0; i < FUSE; i++) a += fused[i] * Wa[i * KD + t];
        out[B_ + b * KD + t] = a;
    } else if (t == KD) {
        float a = bs[0];
        for (int i = 0; i < FUSE; i++) a += fused[i] * Ws[i];
        out[b] = a;
    }
}

// ---------------------------------------------------------------------------
typedef CUresult (CUDAAPI *tmap_enc_t)(
    CUtensorMap*, CUtensorMapDataType, cuuint32_t, void*,
    const cuuint64_t*, const cuuint64_t*, const cuuint32_t*, const cuuint32_t*,
    CUtensorMapInterleave, CUtensorMapSwizzle, CUtensorMapL2promotion,
    CUtensorMapFloatOOBfill);

static void make_map(tmap_enc_t enc, CUtensorMap* m, const void* ptr,
                     CUtensorMapDataType dt, uint64_t d0, uint64_t d1,
                     uint64_t stride1_bytes, uint32_t box0, uint32_t box1) {
    cuuint64_t dims[2]    = {d0, d1};
    cuuint64_t strides[1] = {stride1_bytes};
    cuuint32_t box[2]     = {box0, box1};
    cuuint32_t es[2]      = {1, 1};
    enc(m, dt, 2, (void*)ptr, dims, strides, box, es,
        CU_TENSOR_MAP_INTERLEAVE_NONE, CU_TENSOR_MAP_SWIZZLE_128B,
        CU_TENSOR_MAP_L2_PROMOTION_L2_128B, CU_TENSOR_MAP_FLOAT_OOB_FILL_NONE);
}

extern "C" void kernel_launch(void* const* d_in, const int* in_sizes, int n_in,
                              void* d_out, int out_size) {
    const float* A    = (const float*)d_in[0];
    const float* X    = (const float*)d_in[1];
    const float* gvec = (const float*)d_in[2];
    const float* W1   = (const float*)d_in[3];
    const float* b1   = (const float*)d_in[4];
    const float* g1   = (const float*)d_in[5];
    const float* be1  = (const float*)d_in[6];
    const float* W2   = (const float*)d_in[7];
    const float* b2   = (const float*)d_in[8];
    const float* g2   = (const float*)d_in[9];
    const float* be2  = (const float*)d_in[10];
    const float* Ws   = (const float*)d_in[11];
    const float* bs   = (const float*)d_in[12];
    const float* Wa   = (const float*)d_in[13];
    const float* ba   = (const float*)d_in[14];
    float* out = (float*)d_out;

    const int SMALL_SMEM = 2 * 48 * 1024 + 1024;
    const int BIG_SMEM   = 3 * 64 * 1024 + 1024;
    cudaFuncSetAttribute(k_small_gemm, cudaFuncAttributeMaxDynamicSharedMemorySize, SMALL_SMEM);
    cudaFuncSetAttribute(k_fused1,     cudaFuncAttributeMaxDynamicSharedMemorySize, BIG_SMEM);
    cudaFuncSetAttribute(k_big2,       cudaFuncAttributeMaxDynamicSharedMemorySize, BIG_SMEM);

    float* WT1;
    __half *P1hp, *P2hp, *Ahp, *W2hp;
    cudaGetSymbolAddress((void**)&WT1,  g_WT1);
    cudaGetSymbolAddress((void**)&P1hp, g_P1h);
    cudaGetSymbolAddress((void**)&P2hp, g_P2h);
    cudaGetSymbolAddress((void**)&Ahp,  g_Ah);
    cudaGetSymbolAddress((void**)&W2hp, g_WT2h);

    tmap_enc_t enc = nullptr;
#if CUDART_VERSION >= 12050
    cudaDriverEntryPointQueryResult qr;
    cudaGetDriverEntryPointByVersion("cuTensorMapEncodeTiled", (void**)&enc, 12000,
                                     cudaEnableDefault, &qr);
#else
    cudaGetDriverEntryPoint("cuTensorMapEncodeTiled", (void**)&enc, cudaEnableDefault);
#endif

    CUtensorMap mX, mW1, mAh, mP1h, mP2h, mW2h;
    make_map(enc, &mX,   X,    CU_TENSOR_MAP_DATA_TYPE_FLOAT32, F_, (uint64_t)N_ * B_,
             (uint64_t)F_ * 4, 32, 128);
    make_map(enc, &mW1,  WT1,  CU_TENSOR_MAP_DATA_TYPE_FLOAT32, F_, HD,
             (uint64_t)F_ * 4, 32, 256);
    make_map(enc, &mAh,  Ahp,  CU_TENSOR_MAP_DATA_TYPE_FLOAT16, N_, (uint64_t)N_ * B_,
             (uint64_t)N_ * 2, 64, 256);
    make_map(enc, &mP1h, P1hp, CU_TENSOR_MAP_DATA_TYPE_FLOAT16, N_, (uint64_t)HD * B_,
             (uint64_t)N_ * 2, 64, 256);
    make_map(enc, &mP2h, P2hp, CU_TENSOR_MAP_DATA_TYPE_FLOAT16, N_, (uint64_t)HD * B_,
             (uint64_t)N_ * 2, 64, 256);
    make_map(enc, &mW2h, W2hp, CU_TENSOR_MAP_DATA_TYPE_FLOAT16, HD, HD,
             (uint64_t)HD * 2, 64, 256);

    k_prep<<<256, 256>>>(W1, W2);
    k_convA<<<2048, 256>>>(A);
    k_small_gemm<<<dim3(N_ / 128, B_), 128, SMALL_SMEM>>>(mX, mW1, X);
    k_fused1<<<dim3(N_ / 256, B_), 128, BIG_SMEM>>>(mAh, mP1h, mW2h, A, b1, g1, be1);
    k_big2<<<dim3(N_ / 256, B_), 128, BIG_SMEM>>>(mAh, mP2h, A, b2, g2, be2);
    k_finalize<<<B_, 288>>>(gvec, Ws, bs, Wa, ba, out);
}

// round 14
// speedup vs baseline: 1.1632x; 1.0678x over previous
#include <cuda_runtime.h>
#include <cuda.h>
#include <cuda_fp16.h>
#include <cstdint>
#include <math.h>

#define B_   16
#define N_   2048
#define F_   64
#define HD   256
#define GD   18
#define KD   128
#define FUSE 274
#define LN_EPS 1e-5f

#if defined(__CUDA_ARCH_FEAT_SM103_ALL) || defined(__CUDA_ARCH_FEAT_SM100_ALL) || \
    defined(__CUDA_ARCH_FEAT_SM101_ALL) || \
    (defined(__CUDA_ARCH_SPECIFIC__) && (__CUDA_ARCH_SPECIFIC__ >= 1000)) || \
    (defined(__CUDA_ARCH_FAMILY_SPECIFIC__) && (__CUDA_ARCH_FAMILY_SPECIFIC__ >= 1000))
#define TC_OK 1
#else
#define TC_OK 0
#endif

__device__ __align__(1024) __half g_P1h[B_ * HD * N_];
__device__ __align__(1024) __half g_P2h[B_ * HD * N_];
__device__ __align__(1024) __half g_Ah[(size_t)B_ * N_ * N_];
__device__ __align__(1024) float  g_WT1[HD * F_];
__device__ __align__(1024) __half g_WT2h[HD * HD];
__device__ float g_colsum[B_ * HD];

__device__ __forceinline__ uint32_t smem_u32(const void* p) {
    uint32_t a;
    asm("{ .reg .u64 t; cvta.to.shared.u64 t, %1; cvt.u32.u64 %0, t; }" : "=r"(a) : "l"(p));
    return a;
}
#define SWZ(x) ((x) ^ (((x) >> 3) & 0x70))
#define MBAR_INIT(a, c) \
    asm volatile("mbarrier.init.shared.b64 [%0], %1;" :: "r"(a), "r"(c) : "memory")
#define MBAR_EXPECT_TX(a, n) \
    asm volatile("mbarrier.arrive.expect_tx.shared.b64 _, [%0], %1;" :: "r"(a), "r"(n) : "memory")
#define FENCE_ASYNC() asm volatile("fence.proxy.async.shared::cta;" ::: "memory")

__device__ __forceinline__ void mbar_wait(uint32_t mbar, uint32_t parity) {
    asm volatile(
        "{\n\t.reg .pred P1;\n\t"
        "WL_%=:\n\t"
        "mbarrier.try_wait.parity.acquire.cta.shared::cta.b64 P1, [%0], %1, 0x989680;\n\t"
        "@P1 bra.uni WD_%=;\n\t"
        "bra.uni WL_%=;\n\t"
        "WD_%=:\n\t}"
        :: "r"(mbar), "r"(parity) : "memory");
}

#if TC_OK
__device__ __forceinline__ uint64_t sdesc(uint32_t addr) {
    return ((2ull << 61) | (1ull << 46) | (64ull << 32) | (1ull << 16))
         | ((uint64_t)(addr >> 4) & 0x3FFF);
}
__device__ __forceinline__ void tma2d(uint32_t dst, const CUtensorMap* m, int x, int y,
                                      uint32_t mbar) {
    asm volatile(
        "cp.async.bulk.tensor.2d.shared::cta.global.tile.mbarrier::complete_tx::bytes "
        "[%0], [%1, {%2, %3}], [%4];"
        :: "r"(dst), "l"(m), "r"(x), "r"(y), "r"(mbar) : "memory");
}
#define TC_COMMIT(a) \
    asm volatile("tcgen05.commit.cta_group::1.mbarrier::arrive::one.shared::cluster.b64 [%0];" \
                 :: "r"(a) : "memory")
#define TC_ALLOC(a, n) \
    asm volatile("tcgen05.alloc.cta_group::1.sync.aligned.shared::cta.b32 [%0], %1;" \
                 :: "r"(a), "r"(n) : "memory")
#define TC_RELINQ() \
    asm volatile("tcgen05.relinquish_alloc_permit.cta_group::1.sync.aligned;")
#define TC_DEALLOC(t, n) \
    asm volatile("tcgen05.dealloc.cta_group::1.sync.aligned.b32 %0, %1;" :: "r"(t), "r"(n))
#define TC_FENCE_AFTER()  asm volatile("tcgen05.fence::after_thread_sync;" ::: "memory")
#define TC_FENCE_BEFORE() asm volatile("tcgen05.fence::before_thread_sync;" ::: "memory")
#define TC_WAIT_LD() asm volatile("tcgen05.wait::ld.sync.aligned;" ::: "memory")

#define IDESC_TF32 ((1u << 4) | (2u << 7) | (2u << 10) | (32u << 17) | (8u << 24))
#define IDESC_F16  ((1u << 4) | (32u << 17) | (8u << 24))

__device__ __forceinline__ void mma_tf32(uint32_t d, uint64_t ad, uint64_t bd, uint32_t acc) {
    asm volatile(
        "{\n\t.reg .pred p;\n\tsetp.ne.u32 p, %4, 0;\n\t"
        "tcgen05.mma.cta_group::1.kind::tf32 [%0], %1, %2, %3, p;\n\t}"
        :: "r"(d), "l"(ad), "l"(bd), "r"(IDESC_TF32), "r"(acc) : "memory");
}
__device__ __forceinline__ void mma_f16(uint32_t d, uint64_t ad, uint64_t bd, uint32_t acc) {
    asm volatile(
        "{\n\t.reg .pred p;\n\tsetp.ne.u32 p, %5, 0;\n\t"
        "tcgen05.mma.cta_group::1.kind::f16 [%0], %1, %2, %3, {%4, %4, %4, %4}, p;\n\t}"
        :: "r"(d), "l"(ad), "l"(bd), "r"(IDESC_F16), "r"(0u), "r"(acc) : "memory");
}

#define LDX32(r, a) \
    asm volatile( \
        "tcgen05.ld.sync.aligned.32x32b.x32.b32 " \
        "{%0, %1, %2, %3, %4, %5, %6, %7, %8, %9, %10, %11, %12, %13, %14, %15, " \
        " %16, %17, %18, %19, %20, %21, %22, %23, %24, %25, %26, %27, %28, %29, %30, %31}, [%32];" \
        : "=r"((r)[0]),  "=r"((r)[1]),  "=r"((r)[2]),  "=r"((r)[3]), \
          "=r"((r)[4]),  "=r"((r)[5]),  "=r"((r)[6]),  "=r"((r)[7]), \
          "=r"((r)[8]),  "=r"((r)[9]),  "=r"((r)[10]), "=r"((r)[11]), \
          "=r"((r)[12]), "=r"((r)[13]), "=r"((r)[14]), "=r"((r)[15]), \
          "=r"((r)[16]), "=r"((r)[17]), "=r"((r)[18]), "=r"((r)[19]), \
          "=r"((r)[20]), "=r"((r)[21]), "=r"((r)[22]), "=r"((r)[23]), \
          "=r"((r)[24]), "=r"((r)[25]), "=r"((r)[26]), "=r"((r)[27]), \
          "=r"((r)[28]), "=r"((r)[29]), "=r"((r)[30]), "=r"((r)[31]) \
        : "r"(a))
#endif

// ---------------------------------------------------------------------------
__global__ __launch_bounds__(256) void k_prep(const float* __restrict__ W1,
                                              const float* __restrict__ W2) {
    const int t = threadIdx.x, bx = blockIdx.x;
    if (bx < 16) g_colsum[bx * 256 + t] = 0.f;
    if (bx < F_) g_WT1[t * F_ + bx] = W1[bx * 256 + t];
    g_WT2h[t * HD + bx] = __float2half(W2[bx * 256 + t]);
}

__global__ __launch_bounds__(256) void k_convA(const float* __restrict__ A) {
    const float4* src = (const float4*)A;
    __half2* dst = (__half2*)g_Ah;
    const size_t total = (size_t)B_ * N_ * N_ / 4;
    for (size_t i = (size_t)blockIdx.x * 256 + threadIdx.x; i < total;
         i += (size_t)gridDim.x * 256) {
        float4 v = src[i];
        dst[2 * i]     = __floats2half2_rn(v.x, v.y);
        dst[2 * i + 1] = __floats2half2_rn(v.z, v.w);
    }
}

// ---------------------------------------------------------------------------
// Small GEMM (tf32): P1h^T = (X @ W1)^T
// ---------------------------------------------------------------------------
__global__ __launch_bounds__(128, 1)
void k_small_gemm(const __grid_constant__ CUtensorMap mapIn,
                  const __grid_constant__ CUtensorMap mapW,
                  const float* __restrict__ In) {
    const int tid = threadIdx.x, b = blockIdx.y, m0 = blockIdx.x * 128;
    __half* PTb = g_P1h + (size_t)b * HD * N_;
#if TC_OK
    constexpr int STG = 48 * 1024;
    extern __shared__ char dyn[];
    const uint32_t sbase = (smem_u32(dyn) + 1023) & ~1023u;
    __shared__ __align__(8) uint64_t s_bar[3];
    __shared__ uint32_t s_tmem[1];
    const int wid = tid >> 5, lane = tid & 31;
    const uint32_t bar0 = smem_u32(s_bar);

    if (tid == 0) for (int i = 0; i < 3; i++) MBAR_INIT(bar0 + i * 8, 1);
    if (wid == 0) { TC_ALLOC(smem_u32(s_tmem), 256); TC_RELINQ(); }
    __syncthreads();
    uint32_t tmem;
    asm volatile("ld.shared.b32 %0, [%1];" : "=r"(tmem) : "r"(smem_u32(s_tmem)));

    if (tid == 0) {
        const int yA = b * N_ + m0;
        for (int t = 0; t < 2; t++) {
            uint32_t sa = sbase + t * STG;
            MBAR_EXPECT_TX(bar0 + t * 8, STG);
            tma2d(sa,             &mapIn, t * 32, yA, bar0 + t * 8);
            tma2d(sa + 16 * 1024, &mapW,  t * 32, 0,  bar0 + t * 8);
        }
        for (int t = 0; t < 2; t++) {
            mbar_wait(bar0 + t * 8, 0);
            uint64_t a0 = sdesc(sbase + t * STG), b0 = sdesc(sbase + t * STG + 16 * 1024);
#pragma unroll
            for (int ks = 0; ks < 4; ks++)
                mma_tf32(tmem, a0 + ks * 2, b0 + ks * 2, (t > 0 || ks > 0) ? 1u : 0u);
        }
        TC_COMMIT(bar0 + 16);
    }
    mbar_wait(bar0 + 16, 0);
    TC_FENCE_AFTER();
    const int row = m0 + wid * 32 + lane;
#pragma unroll
    for (int c8 = 0; c8 < 8; c8++) {
        uint32_t r[32];
        LDX32(r, tmem + c8 * 32); TC_WAIT_LD();
#pragma unroll
        for (int j = 0; j < 32; j++)
            PTb[(size_t)(c8 * 32 + j) * N_ + row] = __float2half(__uint_as_float(r[j]));
    }
    __syncthreads();
    if (wid == 0) TC_DEALLOC(tmem, 256);
#else
    for (int idx = tid; idx < 128 * 256; idx += 128) {
        int m = idx >> 8, c = idx & 255;
        float acc = 0.f;
        const float* Inb = In + (size_t)b * N_ * F_ + (size_t)(m0 + m) * F_;
        for (int k = 0; k < F_; k++) acc += Inb[k] * g_WT1[(size_t)c * F_ + k];
        PTb[(size_t)c * N_ + m0 + m] = __float2half(acc);
    }
#endif
}

// ---------------------------------------------------------------------------
// Warp-specialized f16 mainloop (shared by fused1/big2).
// thread 0 = MMA consumer, thread 32 = TMA producer.
// ---------------------------------------------------------------------------
#if TC_OK
__device__ __forceinline__ void mainloop_ws(
    int tid, uint32_t sbase, uint32_t bar0, uint32_t tmem,
    const CUtensorMap* mapA, const CUtensorMap* mapP, int yA, int yB) {
    constexpr int NK = 32, STG = 64 * 1024;
    if (tid == 32) {                       // producer
        int ep[3] = {0, 0, 0};
#pragma unroll 1
        for (int t = 0; t < NK; t++) {
            int s = t % 3;
            if (t >= 3) { mbar_wait(bar0 + 24 + s * 8, ep[s]); ep[s] ^= 1; }
            MBAR_EXPECT_TX(bar0 + s * 8, STG);
            tma2d(sbase + s * STG,             mapA, t * 64, yA, bar0 + s * 8);
            tma2d(sbase + s * STG + 32 * 1024, mapP, t * 64, yB, bar0 + s * 8);
        }
    } else if (tid == 0) {                 // consumer
        int fp[3] = {0, 0, 0};
#pragma unroll 1
        for (int t = 0; t < NK; t++) {
            int s = t % 3;
            mbar_wait(bar0 + s * 8, fp[s]); fp[s] ^= 1;
            uint64_t a0 = sdesc(sbase + s * STG);
            uint64_t a1 = sdesc(sbase + s * STG + 16 * 1024);
            uint64_t b0 = sdesc(sbase + s * STG + 32 * 1024);
#pragma unroll
            for (int ks = 0; ks < 4; ks++) {
                uint32_t acc = (t > 0 || ks > 0) ? 1u : 0u;
                mma_f16(tmem,       a0 + ks * 2, b0 + ks * 2, acc);
                mma_f16(tmem + 256, a1 + ks * 2, b0 + ks * 2, acc);
            }
            TC_COMMIT(bar0 + 24 + s * 8);
        }
        TC_COMMIT(bar0 + 48);
    }
    mbar_wait(bar0 + 48, 0);
}
#endif

// ---------------------------------------------------------------------------
// Fused layer-1: f16 WS mainloop; epilogue LN+ReLU -> y smem, full-W2 preload,
// single back-to-back f16 GEMM chain per half; P2h stored fp16.
// ---------------------------------------------------------------------------
__global__ __launch_bounds__(128, 1)
void k_fused1(const __grid_constant__ CUtensorMap mapAh,
              const __grid_constant__ CUtensorMap mapPh,
              const __grid_constant__ CUtensorMap mapW2h,
              const float* __restrict__ A,
              const float* __restrict__ bias, const float* __restrict__ gamma,
              const float* __restrict__ beta) {
    extern __shared__ char dyn[];
    const int tid = threadIdx.x, b = blockIdx.y, m0 = blockIdx.x * 256;
#if TC_OK
    constexpr int W2OFF = 64 * 1024;       // after drain: y 0..64K, W2 64K..192K
    const uint32_t sbase = (smem_u32(dyn) + 1023) & ~1023u;
    const uint32_t abase = sbase - smem_u32(dyn);
    __shared__ __align__(8) uint64_t s_bar[9];
    __shared__ uint32_t s_tmem[1];
    __shared__ float sb[256], sg[256], st[256];
    const int wid = tid >> 5, lane = tid & 31;
    const uint32_t bar0 = smem_u32(s_bar);
    // full[3]=+0, empty[3]=+24, final=+48, w2=+56, efin=+64

    if (tid == 0) for (int i = 0; i < 9; i++) MBAR_INIT(bar0 + i * 8, 1);
    if (wid == 0) { TC_ALLOC(smem_u32(s_tmem), 512); TC_RELINQ(); }
    __syncthreads();
    uint32_t tmem;
    asm volatile("ld.shared.b32 %0, [%1];" : "=r"(tmem) : "r"(smem_u32(s_tmem)));

    if (tid >= 64)
        for (int i = tid - 64; i < 256; i += 64) {
            sb[i] = bias[i]; sg[i] = gamma[i]; st[i] = beta[i];
        }

    mainloop_ws(tid, sbase, bar0, tmem, &mapAh, &mapPh, b * N_ + m0, b * HD);
    __syncthreads();
    TC_FENCE_AFTER();

    // preload full W2 (128KB) — overlaps with LN passes below
    if (tid == 0) {
        MBAR_EXPECT_TX(bar0 + 56, 131072);
#pragma unroll
        for (int c = 0; c < 4; c++)
            tma2d(sbase + W2OFF + c * 32768, &mapW2h, c * 64, 0, bar0 + 56);
    }

    int eep = 0;
#pragma unroll 1
    for (int half = 0; half < 2; half++) {
        const int row = wid * 32 + lane;
        const uint32_t dbase = tmem + half * 256;
        float sum = 0.f, sq = 0.f;
#pragma unroll 1
        for (int c8 = 0; c8 < 8; c8++) {
            uint32_t r[32];
            LDX32(r, dbase + c8 * 32); TC_WAIT_LD();
#pragma unroll
            for (int j = 0; j < 32; j++) {
                float v = __uint_as_float(r[j]) + sb[c8 * 32 + j];
                sum += v; sq += v * v;
            }
        }
        const float mu = sum * (1.f / HD);
        const float rs = rsqrtf(sq * (1.f / HD) - mu * mu + LN_EPS);

#pragma unroll 1
        for (int c8 = 0; c8 < 8; c8++) {
            uint32_t r[32];
            LDX32(r, dbase + c8 * 32); TC_WAIT_LD();
            float y[32];
#pragma unroll
            for (int j = 0; j < 32; j++) {
                float v = __uint_as_float(r[j]) + sb[c8 * 32 + j];
                y[j] = fmaxf((v - mu) * rs * sg[c8 * 32 + j] + st[c8 * 32 + j], 0.f);
            }
            char* ybase = dyn + abase + (c8 >> 1) * 16384;
            const int off = (c8 & 1) * 64;
#pragma unroll
            for (int q = 0; q < 4; q++) {
                __half2 h[4];
#pragma unroll
                for (int p = 0; p < 4; p++)
                    h[p] = __floats2half2_rn(y[q * 8 + 2 * p], y[q * 8 + 2 * p + 1]);
                *(float4*)(ybase + SWZ(row * 128 + off + q * 16)) = *(float4*)h;
            }
        }
        TC_FENCE_BEFORE();
        FENCE_ASYNC();
        __syncthreads();

        if (tid == 0) {
            if (half == 0) mbar_wait(bar0 + 56, 0);   // W2 resident
#pragma unroll
            for (int c = 0; c < 4; c++) {
                uint64_t yd = sdesc(sbase + c * 16384);
                uint64_t wd = sdesc(sbase + W2OFF + c * 32768);
#pragma unroll
                for (int ks = 0; ks < 4; ks++)
                    mma_f16(tmem + half * 256, yd + ks * 2, wd + ks * 2,
                            (c > 0 || ks > 0) ? 1u : 0u);
            }
            TC_COMMIT(bar0 + 64);
        }
        mbar_wait(bar0 + 64, eep & 1); eep++;
        TC_FENCE_AFTER();

        __half* PTb = g_P2h + (size_t)b * HD * N_;
        const int grow = m0 + half * 128 + row;
#pragma unroll 1
        for (int c8 = 0; c8 < 8; c8++) {
            uint32_t r[32];
            LDX32(r, dbase + c8 * 32); TC_WAIT_LD();
#pragma unroll
            for (int j = 0; j < 32; j++)
                PTb[(size_t)(c8 * 32 + j) * N_ + grow] = __float2half(__uint_as_float(r[j]));
        }
        TC_FENCE_BEFORE();
        __syncthreads();
    }
    if (wid == 0) TC_DEALLOC(tmem, 512);
#else
    const float* Ab = A + (size_t)b * N_ * N_ + (size_t)m0 * N_;
    const __half* Bb = g_P1h + (size_t)b * HD * N_;
    __half* PTb = g_P2h + (size_t)b * HD * N_;
    __shared__ float arow[N_];
    __shared__ float drow[256];
    __shared__ float red[2][4];
    const int lane = tid & 31, wid = tid >> 5;
    for (int m = 0; m < 256; m++) {
        for (int i = tid; i < N_ / 4; i += 128)
            ((float4*)arow)[i] = ((const float4*)(Ab + (size_t)m * N_))[i];
        __syncthreads();
        for (int cp = 0; cp < 2; cp++) {
            int c = tid + cp * 128;
            float acc = 0.f;
            const __half* Brow = Bb + (size_t)c * N_;
            for (int k = 0; k < N_; k++) acc += arow[k] * __half2float(Brow[k]);
            drow[c] = acc + bias[c];
        }
        __syncthreads();
        float v0 = drow[tid], v1 = drow[tid + 128];
        float s = v0 + v1, q = v0 * v0 + v1 * v1;
        for (int o = 16; o > 0; o >>= 1) {
            s += __shfl_xor_sync(0xffffffff, s, o);
            q += __shfl_xor_sync(0xffffffff, q, o);
        }
        if (lane == 0) { red[0][wid] = s; red[1][wid] = q; }
        __syncthreads();
        float ts = red[0][0] + red[0][1] + red[0][2] + red[0][3];
        float tq = red[1][0] + red[1][1] + red[1][2] + red[1][3];
        float mu = ts * (1.f / HD);
        float rsv = rsqrtf(tq * (1.f / HD) - mu * mu + LN_EPS);
        drow[tid]       = fmaxf((v0 - mu) * rsv * gamma[tid] + beta[tid], 0.f);
        drow[tid + 128] = fmaxf((v1 - mu) * rsv * gamma[tid + 128] + beta[tid + 128], 0.f);
        __syncthreads();
        for (int cp = 0; cp < 2; cp++) {
            int c = tid + cp * 128;
            float acc = 0.f;
            for (int k = 0; k < HD; k++)
                acc += drow[k] * __half2float(g_WT2h[(size_t)c * HD + k]);
            PTb[(size_t)c * N_ + m0 + m] = __float2half(acc);
        }
        __syncthreads();
    }
#endif
}

// ---------------------------------------------------------------------------
// Layer-2 big GEMM (f16 WS mainloop): colsum += relu(LN(A_h @ P2h^T + b2))
// ---------------------------------------------------------------------------
__global__ __launch_bounds__(128, 1)
void k_big2(const __grid_constant__ CUtensorMap mapAh,
            const __grid_constant__ CUtensorMap mapPh,
            const float* __restrict__ A,
            const float* __restrict__ bias, const float* __restrict__ gamma,
            const float* __restrict__ beta) {
    extern __shared__ char dyn[];
    const int tid = threadIdx.x, b = blockIdx.y, m0 = blockIdx.x * 256;
#if TC_OK
    const uint32_t sbase = (smem_u32(dyn) + 1023) & ~1023u;
    __shared__ __align__(8) uint64_t s_bar[7];
    __shared__ uint32_t s_tmem[1];
    __shared__ float sb[256], sg[256], st[256];
    const int wid = tid >> 5, lane = tid & 31;
    const uint32_t bar0 = smem_u32(s_bar);

    if (tid == 0) for (int i = 0; i < 7; i++) MBAR_INIT(bar0 + i * 8, 1);
    if (wid == 0) { TC_ALLOC(smem_u32(s_tmem), 512); TC_RELINQ(); }
    __syncthreads();
    uint32_t tmem;
    asm volatile("ld.shared.b32 %0, [%1];" : "=r"(tmem) : "r"(smem_u32(s_tmem)));

    if (tid >= 64)
        for (int i = tid - 64; i < 256; i += 64) {
            sb[i] = bias[i]; sg[i] = gamma[i]; st[i] = beta[i];
        }

    mainloop_ws(tid, sbase, bar0, tmem, &mapAh, &mapPh, b * N_ + m0, b * HD);
    __syncthreads();
    TC_FENCE_AFTER();

    float* wsc = (float*)(dyn) + wid * 33 * 32;
#pragma unroll 1
    for (int half = 0; half < 2; half++) {
        const uint32_t dbase = tmem + half * 256;
        float sum = 0.f, sq = 0.f;
#pragma unroll 1
        for (int c8 = 0; c8 < 8; c8++) {
            uint32_t r[32];
            LDX32(r, dbase + c8 * 32); TC_WAIT_LD();
#pragma unroll
            for (int j = 0; j < 32; j++) {
                float v = __uint_as_float(r[j]) + sb[c8 * 32 + j];
                sum += v; sq += v * v;
            }
        }
        const float mu = sum * (1.f / HD);
        const float rs = rsqrtf(sq * (1.f / HD) - mu * mu + LN_EPS);
#pragma unroll 1
        for (int c8 = 0; c8 < 8; c8++) {
            uint32_t r[32];
            LDX32(r, dbase + c8 * 32); TC_WAIT_LD();
#pragma unroll
            for (int j = 0; j < 32; j++) {
                float v = __uint_as_float(r[j]) + sb[c8 * 32 + j];
                wsc[lane * 33 + j] =
                    fmaxf((v - mu) * rs * sg[c8 * 32 + j] + st[c8 * 32 + j], 0.f);
            }
            __syncwarp();
            float s2 = 0.f;
#pragma unroll
            for (int r2 = 0; r2 < 32; r2++) s2 += wsc[r2 * 33 + lane];
            atomicAdd(&g_colsum[b * HD + c8 * 32 + lane], s2);
            __syncwarp();
        }
    }
    __syncthreads();
    if (wid == 0) TC_DEALLOC(tmem, 512);
#else
    const float* Ab = A + (size_t)b * N_ * N_ + (size_t)m0 * N_;
    const __half* Bb = g_P2h + (size_t)b * HD * N_;
    __shared__ float arow[N_];
    __shared__ float drow[256];
    __shared__ float red[2][4];
    const int lane = tid & 31, wid = tid >> 5;
    float csum0 = 0.f, csum1 = 0.f;
    for (int m = 0; m < 256; m++) {
        for (int i = tid; i < N_ / 4; i += 128)
            ((float4*)arow)[i] = ((const float4*)(Ab + (size_t)m * N_))[i];
        __syncthreads();
        for (int cp = 0; cp < 2; cp++) {
            int c = tid + cp * 128;
            float acc = 0.f;
            const __half* Brow = Bb + (size_t)c * N_;
            for (int k = 0; k < N_; k++) acc += arow[k] * __half2float(Brow[k]);
            drow[c] = acc + bias[c];
        }
        __syncthreads();
        float v0 = drow[tid], v1 = drow[tid + 128];
        float s = v0 + v1, q = v0 * v0 + v1 * v1;
        for (int o = 16; o > 0; o >>= 1) {
            s += __shfl_xor_sync(0xffffffff, s, o);
            q += __shfl_xor_sync(0xffffffff, q, o);
        }
        if (lane == 0) { red[0][wid] = s; red[1][wid] = q; }
        __syncthreads();
        float ts = red[0][0] + red[0][1] + red[0][2] + red[0][3];
        float tq = red[1][0] + red[1][1] + red[1][2] + red[1][3];
        float mu = ts * (1.f / HD);
        float rsv = rsqrtf(tq * (1.f / HD) - mu * mu + LN_EPS);
        csum0 += fmaxf((v0 - mu) * rsv * gamma[tid] + beta[tid], 0.f);
        csum1 += fmaxf((v1 - mu) * rsv * gamma[tid + 128] + beta[tid + 128], 0.f);
        __syncthreads();
    }
    atomicAdd(&g_colsum[b * HD + tid], csum0);
    atomicAdd(&g_colsum[b * HD + tid + 128], csum1);
#endif
}

// ---------------------------------------------------------------------------
__global__ __launch_bounds__(288)
void k_finalize(const float* __restrict__ gvec,
                const float* __restrict__ Ws, const float* __restrict__ bs,
                const float* __restrict__ Wa, const float* __restrict__ ba,
                float* __restrict__ out) {
    __shared__ float fused[FUSE];
    const int b = blockIdx.x, t = threadIdx.x;
    if (t < HD)        fused[t] = g_colsum[b * HD + t] * (1.f / N_);
    else if (t < FUSE) fused[t] = gvec[b * GD + (t - HD)];
    __syncthreads();
    if (t < KD) {
        float a = ba[t];
        for (int i = 0; i < FUSE; i++) a += fused[i] * Wa[i * KD + t];
        out[B_ + b * KD + t] = a;
    } else if (t == KD) {
        float a = bs[0];
        for (int i = 0; i < FUSE; i++) a += fused[i] * Ws[i];
        out[b] = a;
    }
}

// ---------------------------------------------------------------------------
typedef CUresult (CUDAAPI *tmap_enc_t)(
    CUtensorMap*, CUtensorMapDataType, cuuint32_t, void*,
    const cuuint64_t*, const cuuint64_t*, const cuuint32_t*, const cuuint32_t*,
    CUtensorMapInterleave, CUtensorMapSwizzle, CUtensorMapL2promotion,
    CUtensorMapFloatOOBfill);

static void make_map(tmap_enc_t enc, CUtensorMap* m, const void* ptr,
                     CUtensorMapDataType dt, uint64_t d0, uint64_t d1,
                     uint64_t stride1_bytes, uint32_t box0, uint32_t box1) {
    cuuint64_t dims[2]    = {d0, d1};
    cuuint64_t strides[1] = {stride1_bytes};
    cuuint32_t box[2]     = {box0, box1};
    cuuint32_t es[2]      = {1, 1};
    enc(m, dt, 2, (void*)ptr, dims, strides, box, es,
        CU_TENSOR_MAP_INTERLEAVE_NONE, CU_TENSOR_MAP_SWIZZLE_128B,
        CU_TENSOR_MAP_L2_PROMOTION_L2_128B, CU_TENSOR_MAP_FLOAT_OOB_FILL_NONE);
}

extern "C" void kernel_launch(void* const* d_in, const int* in_sizes, int n_in,
                              void* d_out, int out_size) {
    const float* A    = (const float*)d_in[0];
    const float* X    = (const float*)d_in[1];
    const float* gvec = (const float*)d_in[2];
    const float* W1   = (const float*)d_in[3];
    const float* b1   = (const float*)d_in[4];
    const float* g1   = (const float*)d_in[5];
    const float* be1  = (const float*)d_in[6];
    const float* W2   = (const float*)d_in[7];
    const float* b2   = (const float*)d_in[8];
    const float* g2   = (const float*)d_in[9];
    const float* be2  = (const float*)d_in[10];
    const float* Ws   = (const float*)d_in[11];
    const float* bs   = (const float*)d_in[12];
    const float* Wa   = (const float*)d_in[13];
    const float* ba   = (const float*)d_in[14];
    float* out = (float*)d_out;

    const int SMALL_SMEM = 2 * 48 * 1024 + 1024;
    const int BIG_SMEM   = 3 * 64 * 1024 + 1024;
    cudaFuncSetAttribute(k_small_gemm, cudaFuncAttributeMaxDynamicSharedMemorySize, SMALL_SMEM);
    cudaFuncSetAttribute(k_fused1,     cudaFuncAttributeMaxDynamicSharedMemorySize, BIG_SMEM);
    cudaFuncSetAttribute(k_big2,       cudaFuncAttributeMaxDynamicSharedMemorySize, BIG_SMEM);

    float* WT1;
    __half *P1hp, *P2hp, *Ahp, *W2hp;
    cudaGetSymbolAddress((void**)&WT1,  g_WT1);
    cudaGetSymbolAddress((void**)&P1hp, g_P1h);
    cudaGetSymbolAddress((void**)&P2hp, g_P2h);
    cudaGetSymbolAddress((void**)&Ahp,  g_Ah);
    cudaGetSymbolAddress((void**)&W2hp, g_WT2h);

    tmap_enc_t enc = nullptr;
#if CUDART_VERSION >= 12050
    cudaDriverEntryPointQueryResult qr;
    cudaGetDriverEntryPointByVersion("cuTensorMapEncodeTiled", (void**)&enc, 12000,
                                     cudaEnableDefault, &qr);
#else
    cudaGetDriverEntryPoint("cuTensorMapEncodeTiled", (void**)&enc, cudaEnableDefault);
#endif

    CUtensorMap mX, mW1, mAh, mP1h, mP2h, mW2h;
    make_map(enc, &mX,   X,    CU_TENSOR_MAP_DATA_TYPE_FLOAT32, F_, (uint64_t)N_ * B_,
             (uint64_t)F_ * 4, 32, 128);
    make_map(enc, &mW1,  WT1,  CU_TENSOR_MAP_DATA_TYPE_FLOAT32, F_, HD,
             (uint64_t)F_ * 4, 32, 256);
    make_map(enc, &mAh,  Ahp,  CU_TENSOR_MAP_DATA_TYPE_FLOAT16, N_, (uint64_t)N_ * B_,
             (uint64_t)N_ * 2, 64, 256);
    make_map(enc, &mP1h, P1hp, CU_TENSOR_MAP_DATA_TYPE_FLOAT16, N_, (uint64_t)HD * B_,
             (uint64_t)N_ * 2, 64, 256);
    make_map(enc, &mP2h, P2hp, CU_TENSOR_MAP_DATA_TYPE_FLOAT16, N_, (uint64_t)HD * B_,
             (uint64_t)N_ * 2, 64, 256);
    make_map(enc, &mW2h, W2hp, CU_TENSOR_MAP_DATA_TYPE_FLOAT16, HD, HD,
             (uint64_t)HD * 2, 64, 256);

    k_prep<<<256, 256>>>(W1, W2);
    k_convA<<<2048, 256>>>(A);
    k_small_gemm<<<dim3(N_ / 128, B_), 128, SMALL_SMEM>>>(mX, mW1, X);
    k_fused1<<<dim3(N_ / 256, B_), 128, BIG_SMEM>>>(mAh, mP1h, mW2h, A, b1, g1, be1);
    k_big2<<<dim3(N_ / 256, B_), 128, BIG_SMEM>>>(mAh, mP2h, A, b2, g2, be2);
    k_finalize<<<B_, 288>>>(gvec, Ws, bs, Wa, ba, out);
}